// round 12
// baseline (speedup 1.0000x reference)
#include <cuda_runtime.h>
#include <cuda_bf16.h>
#include <cuda_fp16.h>
#include <math.h>
#include <stdint.h>

// ---------------- problem constants ----------------
#define D_MODEL  768
#define N_LAYERS 2
#define D_STATE  16
#define VOCAB    32000
#define D_INNER  1536            // 2*D_MODEL
#define BATCH    2
#define SEQ      2048
#define NTOK     (BATCH*SEQ)     // 4096
#define LN_EPS   1e-5f

// ---------------- scratch (device globals; no mallocs allowed) ----------------
__device__ static float g_x [NTOK * D_MODEL];
__device__ static float g_xp[NTOK * 2 * D_INNER];
__device__ static float g_dt[NTOK * D_INNER];
__device__ static float g_Bm[NTOK * D_STATE];
__device__ static float g_Cm[NTOK * D_STATE];
__device__ static float g_o [NTOK * D_MODEL];
// bf16 split operands (layer GEMMs, 3-term)
__device__ static __nv_bfloat16 g_xhi[NTOK * D_MODEL];
__device__ static __nv_bfloat16 g_xlo[NTOK * D_MODEL];
__device__ static __nv_bfloat16 g_yhi[NTOK * D_INNER];
__device__ static __nv_bfloat16 g_ylo[NTOK * D_INNER];
__device__ static __nv_bfloat16 g_wihi[N_LAYERS * 2 * D_INNER * D_MODEL];
__device__ static __nv_bfloat16 g_wilo[N_LAYERS * 2 * D_INNER * D_MODEL];
__device__ static __nv_bfloat16 g_wdhi[N_LAYERS * D_INNER * D_MODEL];
__device__ static __nv_bfloat16 g_wdlo[N_LAYERS * D_INNER * D_MODEL];
__device__ static __nv_bfloat16 g_wohi[N_LAYERS * D_MODEL * D_INNER];
__device__ static __nv_bfloat16 g_wolo[N_LAYERS * D_MODEL * D_INNER];
// fp16 operands (logits GEMM, plain fp16 x fp16)
__device__ static __half g_xf16[NTOK * D_MODEL];
__device__ static __half g_ef16[VOCAB * D_MODEL];

// ======================= helpers =======================
#define SW128X(o) ((o) ^ (((o) >> 3) & 0x70))

__device__ __forceinline__ uint32_t s2u(const void* p) {
    uint32_t a;
    asm("{ .reg .u64 t; cvta.to.shared.u64 t, %1; cvt.u32.u64 %0, t; }"
        : "=r"(a) : "l"(p));
    return a;
}

__device__ __forceinline__ void ldsm4(uint32_t* r, uint32_t addr) {
    asm volatile("ldmatrix.sync.aligned.m8n8.x4.shared.b16 {%0,%1,%2,%3}, [%4];"
                 : "=r"(r[0]), "=r"(r[1]), "=r"(r[2]), "=r"(r[3]) : "r"(addr));
}

__device__ __forceinline__ void mma_bf16(float* c, const uint32_t* a,
                                         uint32_t b0, uint32_t b1) {
    asm volatile(
        "mma.sync.aligned.m16n8k16.row.col.f32.bf16.bf16.f32 "
        "{%0,%1,%2,%3}, {%4,%5,%6,%7}, {%8,%9}, {%0,%1,%2,%3};"
        : "+f"(c[0]), "+f"(c[1]), "+f"(c[2]), "+f"(c[3])
        : "r"(a[0]), "r"(a[1]), "r"(a[2]), "r"(a[3]), "r"(b0), "r"(b1));
}

__device__ __forceinline__ void mma_fp16(float* c, const uint32_t* a,
                                         uint32_t b0, uint32_t b1) {
    asm volatile(
        "mma.sync.aligned.m16n8k16.row.col.f32.f16.f16.f32 "
        "{%0,%1,%2,%3}, {%4,%5,%6,%7}, {%8,%9}, {%0,%1,%2,%3};"
        : "+f"(c[0]), "+f"(c[1]), "+f"(c[2]), "+f"(c[3])
        : "r"(a[0]), "r"(a[1]), "r"(a[2]), "r"(a[3]), "r"(b0), "r"(b1));
}

__device__ __forceinline__ void cp16(uint32_t saddr, const void* gaddr) {
    asm volatile("cp.async.ca.shared.global [%0], [%1], 16;"
                 :: "r"(saddr), "l"(gaddr) : "memory");
}

__device__ __forceinline__ uint32_t pack_bf2(float a, float b) {
    __nv_bfloat162 t = __floats2bfloat162_rn(a, b);
    return *(uint32_t*)&t;
}
__device__ __forceinline__ uint32_t pack_hf2(float a, float b) {
    __half2 t = __floats2half2_rn(a, b);
    return *(uint32_t*)&t;
}

// =================== split-bf16 tensor GEMM: C = A @ B^T (3-term) ===========
// Proven config: tile 128x128, K-chunk 64, single 64KB stage, 2 CTAs/SM.
#define OPA_H 0
#define OPA_L 16384
#define OPB_H 32768
#define OPB_L 49152
#define GEMM_SMEM 65536

__global__ void __launch_bounds__(256, 2)
gemm_split(const __nv_bfloat16* __restrict__ Ahi, const __nv_bfloat16* __restrict__ Alo,
           const __nv_bfloat16* __restrict__ Bhi, const __nv_bfloat16* __restrict__ Blo,
           float* __restrict__ C, int M, int N, int K,
           int mode, const float* __restrict__ eb1, const float* __restrict__ eb2) {
    extern __shared__ char smc[];
    const uint32_t sb = s2u(smc);
    const int tid = threadIdx.x;
    const int wid = tid >> 5, lid = tid & 31;
    const int wm = wid & 1, wn = wid >> 1;          // warp grid 2(M) x 4(N)
    const int bm = blockIdx.x * 128, bn = blockIdx.y * 128;

    const int rin = lid & 7;
    const uint32_t xr = (uint32_t)rin << 4;
    const int amat = lid >> 3;
    const uint32_t aKq = (uint32_t)(amat >> 1) * 16;
    uint32_t aRow[4];
#pragma unroll
    for (int mt = 0; mt < 4; mt++)
        aRow[mt] = (uint32_t)(wm * 64 + mt * 16 + (amat & 1) * 8 + rin) * 128;
    const int bpair = lid >> 4, bsub = (lid >> 3) & 1;
    const uint32_t bKq = (uint32_t)bsub * 16;
    uint32_t bRow[2];
#pragma unroll
    for (int p = 0; p < 2; p++)
        bRow[p] = (uint32_t)(wn * 32 + p * 16 + bpair * 8 + rin) * 128;

    const int grow = tid >> 1;
    const int gch0 = (tid & 1) * 4;
    uint32_t sOff[4];
#pragma unroll
    for (int j = 0; j < 4; j++)
        sOff[j] = SW128X((uint32_t)grow * 128 + (uint32_t)(gch0 + j) * 16);

    const __nv_bfloat16* gAh = Ahi + (size_t)(bm + grow) * K + gch0 * 8;
    const __nv_bfloat16* gAl = Alo + (size_t)(bm + grow) * K + gch0 * 8;
    const __nv_bfloat16* gBh = Bhi + (size_t)(bn + grow) * K + gch0 * 8;
    const __nv_bfloat16* gBl = Blo + (size_t)(bn + grow) * K + gch0 * 8;

    float acc[4][4][4];
#pragma unroll
    for (int mt = 0; mt < 4; mt++)
#pragma unroll
        for (int nt = 0; nt < 4; nt++)
#pragma unroll
            for (int i = 0; i < 4; i++) acc[mt][nt][i] = 0.f;

    const int NC = K / 64;
    for (int c = 0; c < NC; c++) {
        const int k0 = c * 64;
        __syncthreads();
#pragma unroll
        for (int j = 0; j < 4; j++) {
            cp16(sb + OPA_H + sOff[j], gAh + k0 + j * 8);
            cp16(sb + OPA_L + sOff[j], gAl + k0 + j * 8);
            cp16(sb + OPB_H + sOff[j], gBh + k0 + j * 8);
            cp16(sb + OPB_L + sOff[j], gBl + k0 + j * 8);
        }
        asm volatile("cp.async.commit_group;" ::: "memory");
        asm volatile("cp.async.wait_group 0;" ::: "memory");
        __syncthreads();

#pragma unroll
        for (int ks = 0; ks < 4; ks++) {
            const uint32_t aoff = (((uint32_t)ks * 32 + aKq) ^ xr);
            const uint32_t boff = (((uint32_t)ks * 32 + bKq) ^ xr);
            uint32_t ah[4][4], bb[2][4];
#pragma unroll
            for (int mt = 0; mt < 4; mt++)
                ldsm4(ah[mt], sb + OPA_H + aRow[mt] + aoff);
#pragma unroll
            for (int p = 0; p < 2; p++)
                ldsm4(bb[p], sb + OPB_H + bRow[p] + boff);
#pragma unroll
            for (int mt = 0; mt < 4; mt++)
#pragma unroll
                for (int nt = 0; nt < 4; nt++)
                    mma_bf16(acc[mt][nt], ah[mt],
                             bb[nt >> 1][(nt & 1) * 2], bb[nt >> 1][(nt & 1) * 2 + 1]);
#pragma unroll
            for (int p = 0; p < 2; p++)
                ldsm4(bb[p], sb + OPB_L + bRow[p] + boff);
#pragma unroll
            for (int mt = 0; mt < 4; mt++)
#pragma unroll
                for (int nt = 0; nt < 4; nt++)
                    mma_bf16(acc[mt][nt], ah[mt],
                             bb[nt >> 1][(nt & 1) * 2], bb[nt >> 1][(nt & 1) * 2 + 1]);
#pragma unroll
            for (int mt = 0; mt < 4; mt++)
                ldsm4(ah[mt], sb + OPA_L + aRow[mt] + aoff);
#pragma unroll
            for (int p = 0; p < 2; p++)
                ldsm4(bb[p], sb + OPB_H + bRow[p] + boff);
#pragma unroll
            for (int mt = 0; mt < 4; mt++)
#pragma unroll
                for (int nt = 0; nt < 4; nt++)
                    mma_bf16(acc[mt][nt], ah[mt],
                             bb[nt >> 1][(nt & 1) * 2], bb[nt >> 1][(nt & 1) * 2 + 1]);
        }
    }

    const int gid = lid >> 2, tig = lid & 3;
#pragma unroll
    for (int mt = 0; mt < 4; mt++) {
#pragma unroll
        for (int nt = 0; nt < 4; nt++) {
            int r0 = bm + wm * 64 + mt * 16 + gid;
            int c0 = bn + wn * 32 + nt * 8 + tig * 2;
            float v[4] = {acc[mt][nt][0], acc[mt][nt][1],
                          acc[mt][nt][2], acc[mt][nt][3]};
            if (mode == 1) {
                float bb0 = eb1[c0] + eb2[c0];
                float bb1 = eb1[c0 + 1] + eb2[c0 + 1];
#pragma unroll
                for (int i = 0; i < 4; i++) {
                    float t = v[i] + ((i & 1) ? bb1 : bb0);
                    float sp = (t > 20.f) ? t : log1pf(expf(t));
                    v[i] = fminf(fmaxf(sp, 0.f), 1.f);
                }
            }
            *(float2*)&C[(size_t)r0 * N + c0]       = make_float2(v[0], v[1]);
            *(float2*)&C[(size_t)(r0 + 8) * N + c0] = make_float2(v[2], v[3]);
        }
    }
}

// ============ plain fp16 GEMM: C = A @ B^T (logits only) ==============
// Single fp16 both sides: x-quant (2.06e-4 measured) + emb-quant add in
// quadrature -> ~2.9e-4 predicted. 1 MMA per k16 (was 2).
#define FP_A  0
#define FP_B  16384
#define GEMM16_SMEM 32768

__global__ void __launch_bounds__(256, 2)
gemm_fp16_plain(const __half* __restrict__ A, const __half* __restrict__ B,
                float* __restrict__ C, int M, int N, int K) {
    extern __shared__ char smc[];
    const uint32_t sb = s2u(smc);
    const int tid = threadIdx.x;
    const int wid = tid >> 5, lid = tid & 31;
    const int wm = wid & 1, wn = wid >> 1;
    const int bm = blockIdx.x * 128, bn = blockIdx.y * 128;

    const int rin = lid & 7;
    const uint32_t xr = (uint32_t)rin << 4;
    const int amat = lid >> 3;
    const uint32_t aKq = (uint32_t)(amat >> 1) * 16;
    uint32_t aRow[4];
#pragma unroll
    for (int mt = 0; mt < 4; mt++)
        aRow[mt] = (uint32_t)(wm * 64 + mt * 16 + (amat & 1) * 8 + rin) * 128;
    const int bpair = lid >> 4, bsub = (lid >> 3) & 1;
    const uint32_t bKq = (uint32_t)bsub * 16;
    uint32_t bRow[2];
#pragma unroll
    for (int p = 0; p < 2; p++)
        bRow[p] = (uint32_t)(wn * 32 + p * 16 + bpair * 8 + rin) * 128;

    const int grow = tid >> 1;
    const int gch0 = (tid & 1) * 4;
    uint32_t sOff[4];
#pragma unroll
    for (int j = 0; j < 4; j++)
        sOff[j] = SW128X((uint32_t)grow * 128 + (uint32_t)(gch0 + j) * 16);

    const __half* gA = A + (size_t)(bm + grow) * K + gch0 * 8;
    const __half* gB = B + (size_t)(bn + grow) * K + gch0 * 8;

    float acc[4][4][4];
#pragma unroll
    for (int mt = 0; mt < 4; mt++)
#pragma unroll
        for (int nt = 0; nt < 4; nt++)
#pragma unroll
            for (int i = 0; i < 4; i++) acc[mt][nt][i] = 0.f;

    const int NC = K / 64;
    for (int c = 0; c < NC; c++) {
        const int k0 = c * 64;
        __syncthreads();
#pragma unroll
        for (int j = 0; j < 4; j++) {
            cp16(sb + FP_A + sOff[j], gA + k0 + j * 8);
            cp16(sb + FP_B + sOff[j], gB + k0 + j * 8);
        }
        asm volatile("cp.async.commit_group;" ::: "memory");
        asm volatile("cp.async.wait_group 0;" ::: "memory");
        __syncthreads();

#pragma unroll
        for (int ks = 0; ks < 4; ks++) {
            const uint32_t aoff = (((uint32_t)ks * 32 + aKq) ^ xr);
            const uint32_t boff = (((uint32_t)ks * 32 + bKq) ^ xr);
            uint32_t ah[4][4], bb[2][4];
#pragma unroll
            for (int mt = 0; mt < 4; mt++)
                ldsm4(ah[mt], sb + FP_A + aRow[mt] + aoff);
#pragma unroll
            for (int p = 0; p < 2; p++)
                ldsm4(bb[p], sb + FP_B + bRow[p] + boff);
#pragma unroll
            for (int mt = 0; mt < 4; mt++)
#pragma unroll
                for (int nt = 0; nt < 4; nt++)
                    mma_fp16(acc[mt][nt], ah[mt],
                             bb[nt >> 1][(nt & 1) * 2], bb[nt >> 1][(nt & 1) * 2 + 1]);
        }
    }

    const int gid = lid >> 2, tig = lid & 3;
#pragma unroll
    for (int mt = 0; mt < 4; mt++) {
#pragma unroll
        for (int nt = 0; nt < 4; nt++) {
            int r0 = bm + wm * 64 + mt * 16 + gid;
            int c0 = bn + wn * 32 + nt * 8 + tig * 2;
            *(float2*)&C[(size_t)r0 * N + c0] =
                make_float2(acc[mt][nt][0], acc[mt][nt][1]);
            *(float2*)&C[(size_t)(r0 + 8) * N + c0] =
                make_float2(acc[mt][nt][2], acc[mt][nt][3]);
        }
    }
}

// ------------- vectorized fp32 -> (hi, lo) bf16 split (4 elems/thread) -------------
__global__ void split_kernel(const float* __restrict__ src,
                             __nv_bfloat16* __restrict__ hi,
                             __nv_bfloat16* __restrict__ lo, int n4) {
    int i = blockIdx.x * 256 + threadIdx.x;
    if (i < n4) {
        float4 v = ((const float4*)src)[i];
        float a[4] = {v.x, v.y, v.z, v.w};
        float hf[4], lf[4];
#pragma unroll
        for (int j = 0; j < 4; j++) {
            __nv_bfloat16 h = __float2bfloat16(a[j]);
            hf[j] = __bfloat162float(h);
            lf[j] = a[j] - hf[j];
        }
        ((uint2*)hi)[i] = make_uint2(pack_bf2(hf[0], hf[1]), pack_bf2(hf[2], hf[3]));
        ((uint2*)lo)[i] = make_uint2(pack_bf2(lf[0], lf[1]), pack_bf2(lf[2], lf[3]));
    }
}

// ------------- vectorized fp32 -> fp16 convert ----------------
__global__ void conv_fp16_kernel(const float* __restrict__ src,
                                 __half* __restrict__ dst, int n4) {
    int i = blockIdx.x * 256 + threadIdx.x;
    if (i < n4) {
        float4 v = ((const float4*)src)[i];
        ((uint2*)dst)[i] = make_uint2(pack_hf2(v.x, v.y), pack_hf2(v.z, v.w));
    }
}

// ---------------- embedding gather (+ bf16 split emit) ----------------
__global__ void embed_kernel(const int* __restrict__ ids,
                             const float* __restrict__ emb,
                             float* __restrict__ x,
                             __nv_bfloat16* __restrict__ xhi,
                             __nv_bfloat16* __restrict__ xlo) {
    int row = blockIdx.x;
    int id  = ids[row];
    float4 v = ((const float4*)(emb + (size_t)id * D_MODEL))[threadIdx.x];
    size_t base = (size_t)row * D_MODEL + threadIdx.x * 4;
    ((float4*)(x + (size_t)row * D_MODEL))[threadIdx.x] = v;
    float a[4] = {v.x, v.y, v.z, v.w};
#pragma unroll
    for (int j = 0; j < 4; j++) {
        __nv_bfloat16 h = __float2bfloat16(a[j]);
        xhi[base + j] = h;
        xlo[base + j] = __float2bfloat16(a[j] - __bfloat162float(h));
    }
}

// ---------------- skinny GEMM for B/C projections (N=16 each) ----------------
__global__ __launch_bounds__(256)
void bc_gemm(const float* __restrict__ x, const float* __restrict__ Wb,
             const float* __restrict__ Wc, float* __restrict__ Bm,
             float* __restrict__ Cm) {
    __shared__ float xs[8][D_MODEL];
    int row0 = blockIdx.x * 8;
    const float4* xg = (const float4*)(x + (size_t)row0 * D_MODEL);
    float4* xsv = (float4*)xs;
    for (int i = threadIdx.x; i < 8 * D_MODEL / 4; i += 256) xsv[i] = xg[i];
    __syncthreads();

    int r = threadIdx.x >> 5;
    int c = threadIdx.x & 31;
    const float* W = (c < 16) ? (Wb + (size_t)c * D_MODEL)
                              : (Wc + (size_t)(c - 16) * D_MODEL);
    const float4* Wv = (const float4*)W;
    const float4* xr = (const float4*)xs[r];
    float s = 0.f;
#pragma unroll 4
    for (int k = 0; k < D_MODEL / 4; k++) {
        float4 w = Wv[k], v = xr[k];
        s += w.x * v.x + w.y * v.y + w.z * v.z + w.w * v.w;
    }
    if (c < 16) Bm[(size_t)(row0 + r) * D_STATE + c]        = s;
    else        Cm[(size_t)(row0 + r) * D_STATE + (c - 16)] = s;
}

// ======== SSM scan: staged chunks + FUSED gate/split epilogue ========
// TCH=16 keeps static SMEM at 28KB (<48KB cap) with the extra gate slab.
// Emits yhi/ylo bf16 directly; the separate gate_mul pass and fp32 y
// buffer round-trip are gone.
#define TCH 16
__global__ __launch_bounds__(128)
void ssm_scan(const float* __restrict__ xp, const float* __restrict__ dtc,
              const float* __restrict__ Bm, const float* __restrict__ Cm,
              const float* __restrict__ Amat, const float* __restrict__ Dvec,
              __nv_bfloat16* __restrict__ yhi, __nv_bfloat16* __restrict__ ylo) {
    __shared__ float  xp_s[2][TCH][64];
    __shared__ float  dt_s[2][TCH][64];
    __shared__ float  gt_s[2][TCH][64];
    __shared__ float4 B_s [2][TCH][4];
    __shared__ float4 C_s [2][TCH][4];

    const int tid = threadIdx.x;
    const int wid = tid >> 5, lid = tid & 31;
    const int ch   = wid * 16 + (lid & 15);      // 0..63 local channel
    const int half = lid >> 4;                   // states [0,8) or [8,16)
    const int d0 = blockIdx.x * 64;
    const int d  = d0 + ch;
    const int b  = blockIdx.y;

    float Ar[8], h[8];
#pragma unroll
    for (int j = 0; j < 8; j++) {
        Ar[j] = Amat[(size_t)d * D_STATE + half * 8 + j];
        h[j]  = 0.f;
    }
    const float Dd = Dvec[d];

    const int tt0 = tid >> 4;            // 0..7
    const int seg = (tid & 15) * 4;      // float offset within 64-ch row

    auto issue_chunk = [&](int buf, int tc) {
#pragma unroll
        for (int r = 0; r < 2; r++) {
            int tt = tt0 + r * 8;
            size_t row = (size_t)b * SEQ + tc + tt;
            cp16(s2u(&xp_s[buf][tt][seg]), xp  + row * (2 * D_INNER) + d0 + seg);
            cp16(s2u(&gt_s[buf][tt][seg]), xp  + row * (2 * D_INNER) + D_INNER + d0 + seg);
            cp16(s2u(&dt_s[buf][tt][seg]), dtc + row * D_INNER       + d0 + seg);
        }
        size_t bcbase = ((size_t)b * SEQ + tc) * D_STATE;   // 256 floats / chunk
        if (tid < 64) cp16(s2u((float*)B_s[buf] + tid * 4), Bm + bcbase + tid * 4);
        else cp16(s2u((float*)C_s[buf] + (tid - 64) * 4), Cm + bcbase + (tid - 64) * 4);
        asm volatile("cp.async.commit_group;" ::: "memory");
    };

    issue_chunk(0, 0);
    const int NCH = SEQ / TCH;
    for (int c = 0; c < NCH; c++) {
        const int buf = c & 1;
        if (c + 1 < NCH) {
            issue_chunk(buf ^ 1, (c + 1) * TCH);
            asm volatile("cp.async.wait_group 1;" ::: "memory");
        } else {
            asm volatile("cp.async.wait_group 0;" ::: "memory");
        }
        __syncthreads();

        const int tcg = c * TCH;
#pragma unroll 4
        for (int tt = 0; tt < TCH; tt++) {
            float u  = xp_s[buf][tt][ch];
            float dv = dt_s[buf][tt][ch];
            float4 Bv0 = B_s[buf][tt][half * 2];
            float4 Bv1 = B_s[buf][tt][half * 2 + 1];
            float4 Cv0 = C_s[buf][tt][half * 2];
            float4 Cv1 = C_s[buf][tt][half * 2 + 1];
            float bs[8] = {Bv0.x, Bv0.y, Bv0.z, Bv0.w, Bv1.x, Bv1.y, Bv1.z, Bv1.w};
            float cs[8] = {Cv0.x, Cv0.y, Cv0.z, Cv0.w, Cv1.x, Cv1.y, Cv1.z, Cv1.w};
            float u01 = 0.1f * u;
            float adt = 0.1f * dv;
            float p0 = 0.f, p1 = 0.f;
#pragma unroll
            for (int j = 0; j < 8; j++) {
                float hv = h[j];
                hv = fmaf(hv * Ar[j], adt, fmaf(bs[j], u01, hv));
                h[j] = hv;
                float p = hv * cs[j];
                if (j & 1) p1 += p; else p0 += p;
            }
            float part = p0 + p1;
            float tot = part + __shfl_xor_sync(0xffffffffu, part, 16);
            if (!half) {
                float g = gt_s[buf][tt][ch];
                float v = (Dd * u + tot) * (1.f / (1.f + expf(-g)));
                __nv_bfloat16 hb = __float2bfloat16(v);
                size_t idx = ((size_t)b * SEQ + tcg + tt) * D_INNER + d;
                yhi[idx] = hb;
                ylo[idx] = __float2bfloat16(v - __bfloat162float(hb));
            }
        }
        __syncthreads();
    }
}

// -------- layernorm: out = post? + LN(in + res?) * g + b (+ bf16/fp16 emit) --------
__device__ __forceinline__ float block_reduce(float v, float* red) {
    for (int o = 16; o > 0; o >>= 1) v += __shfl_down_sync(0xffffffffu, v, o);
    if ((threadIdx.x & 31) == 0) red[threadIdx.x >> 5] = v;
    __syncthreads();
    float t = 0.f;
#pragma unroll
    for (int w = 0; w < 8; w++) t += red[w];
    return t;
}

__global__ __launch_bounds__(256)
void ln_kernel(const float* __restrict__ in, const float* __restrict__ res,
               const float* __restrict__ post,
               const float* __restrict__ g, const float* __restrict__ b,
               float* __restrict__ out,
               __nv_bfloat16* __restrict__ ohi, __nv_bfloat16* __restrict__ olo,
               __half* __restrict__ of16) {
    __shared__ float red[8];
    const int row = blockIdx.x;
    const int t   = threadIdx.x;
    float v[3], pv[3];
    float s = 0.f;
#pragma unroll
    for (int i = 0; i < 3; i++) {
        int c = t + i * 256;
        float x = in[(size_t)row * D_MODEL + c];
        if (res) x += res[(size_t)row * D_MODEL + c];
        pv[i] = post ? post[(size_t)row * D_MODEL + c] : 0.f;
        v[i] = x;
        s += x;
    }
    float tot = block_reduce(s, red);
    float mu = tot * (1.f / D_MODEL);
    __syncthreads();
    float q = 0.f;
#pragma unroll
    for (int i = 0; i < 3; i++) {
        float dd = v[i] - mu;
        q += dd * dd;
    }
    float qtot = block_reduce(q, red);
    float rs = rsqrtf(qtot * (1.f / D_MODEL) + LN_EPS);
#pragma unroll
    for (int i = 0; i < 3; i++) {
        int c = t + i * 256;
        float o = pv[i] + (v[i] - mu) * rs * g[c] + b[c];
        size_t idx = (size_t)row * D_MODEL + c;
        out[idx] = o;
        if (ohi) {
            __nv_bfloat16 h = __float2bfloat16(o);
            ohi[idx] = h;
            olo[idx] = __float2bfloat16(o - __bfloat162float(h));
        }
        if (of16) of16[idx] = __float2half(o);
    }
}

// ---------------- launch ----------------
extern "C" void kernel_launch(void* const* d_in, const int* in_sizes, int n_in,
                              void* d_out, int out_size) {
    const int*   input_ids = (const int*)  d_in[0];
    const float* emb       = (const float*)d_in[1];
    const float* W_in      = (const float*)d_in[2];   // [2, 3072, 768]
    const float* W_dt      = (const float*)d_in[3];   // [2, 1536, 768]
    const float* b_dt      = (const float*)d_in[4];
    const float* dt_bias   = (const float*)d_in[5];
    const float* W_B       = (const float*)d_in[6];
    const float* W_C       = (const float*)d_in[7];
    const float* Amat      = (const float*)d_in[8];
    const float* Dvec      = (const float*)d_in[9];
    const float* W_out     = (const float*)d_in[10];  // [2, 768, 1536]
    const float* ln_g      = (const float*)d_in[11];
    const float* ln_b      = (const float*)d_in[12];
    const float* fin_g     = (const float*)d_in[13];
    const float* fin_b     = (const float*)d_in[14];
    float* logits = (float*)d_out;                    // [4096, 32000]

    float *x, *xp, *dt, *Bm, *Cm, *o;
    __nv_bfloat16 *xhi, *xlo, *yhi, *ylo;
    __nv_bfloat16 *wihi, *wilo, *wdhi, *wdlo, *wohi, *wolo;
    __half *xf16, *ef16;
    cudaGetSymbolAddress((void**)&x,  g_x);
    cudaGetSymbolAddress((void**)&xp, g_xp);
    cudaGetSymbolAddress((void**)&dt, g_dt);
    cudaGetSymbolAddress((void**)&Bm, g_Bm);
    cudaGetSymbolAddress((void**)&Cm, g_Cm);
    cudaGetSymbolAddress((void**)&o,  g_o);
    cudaGetSymbolAddress((void**)&xhi, g_xhi);
    cudaGetSymbolAddress((void**)&xlo, g_xlo);
    cudaGetSymbolAddress((void**)&yhi, g_yhi);
    cudaGetSymbolAddress((void**)&ylo, g_ylo);
    cudaGetSymbolAddress((void**)&wihi, g_wihi);
    cudaGetSymbolAddress((void**)&wilo, g_wilo);
    cudaGetSymbolAddress((void**)&wdhi, g_wdhi);
    cudaGetSymbolAddress((void**)&wdlo, g_wdlo);
    cudaGetSymbolAddress((void**)&wohi, g_wohi);
    cudaGetSymbolAddress((void**)&wolo, g_wolo);
    cudaGetSymbolAddress((void**)&xf16, g_xf16);
    cudaGetSymbolAddress((void**)&ef16, g_ef16);

    cudaFuncSetAttribute(gemm_split, cudaFuncAttributeMaxDynamicSharedMemorySize,
                         GEMM_SMEM);
    cudaFuncSetAttribute(gemm_fp16_plain, cudaFuncAttributeMaxDynamicSharedMemorySize,
                         GEMM16_SMEM);

    embed_kernel<<<NTOK, D_MODEL / 4>>>(input_ids, emb, x, xhi, xlo);

    // hoisted weight/emb splits (vectorized, dedicated buffers)
    {
        int n4 = N_LAYERS * 2 * D_INNER * D_MODEL / 4;
        split_kernel<<<(n4 + 255) / 256, 256>>>(W_in, wihi, wilo, n4);
        n4 = N_LAYERS * D_INNER * D_MODEL / 4;
        split_kernel<<<(n4 + 255) / 256, 256>>>(W_dt, wdhi, wdlo, n4);
        n4 = N_LAYERS * D_MODEL * D_INNER / 4;
        split_kernel<<<(n4 + 255) / 256, 256>>>(W_out, wohi, wolo, n4);
        n4 = VOCAB * D_MODEL / 4;
        conv_fp16_kernel<<<(n4 + 255) / 256, 256>>>(emb, ef16, n4);
    }

    for (int l = 0; l < N_LAYERS; l++) {
        const size_t oWi = (size_t)l * 2 * D_INNER * D_MODEL;
        const size_t oWd = (size_t)l * D_INNER * D_MODEL;
        const size_t oWo = (size_t)l * D_MODEL * D_INNER;
        const float* bd = b_dt    + (size_t)l * D_INNER;
        const float* db = dt_bias + (size_t)l * D_INNER;
        const float* Wb = W_B   + (size_t)l * D_STATE * D_MODEL;
        const float* Wc = W_C   + (size_t)l * D_STATE * D_MODEL;
        const float* Al = Amat  + (size_t)l * D_INNER * D_STATE;
        const float* Dl = Dvec  + (size_t)l * D_INNER;
        const float* lg = ln_g  + (size_t)l * D_MODEL;
        const float* lb = ln_b  + (size_t)l * D_MODEL;

        // xp = x @ W_in^T : [4096, 3072]
        gemm_split<<<dim3(NTOK / 128, 2 * D_INNER / 128), 256, GEMM_SMEM>>>(
            xhi, xlo, wihi + oWi, wilo + oWi, xp, NTOK, 2 * D_INNER, D_MODEL,
            0, nullptr, nullptr);
        // dt = softplus/clip(x @ W_dt^T + biases) fused in epilogue
        gemm_split<<<dim3(NTOK / 128, D_INNER / 128), 256, GEMM_SMEM>>>(
            xhi, xlo, wdhi + oWd, wdlo + oWd, dt, NTOK, D_INNER, D_MODEL,
            1, bd, db);
        bc_gemm<<<NTOK / 8, 256>>>(x, Wb, Wc, Bm, Cm);
        // scan + fused gate/sigmoid/split -> yhi/ylo bf16
        ssm_scan<<<dim3(D_INNER / 64, BATCH), 128>>>(xp, dt, Bm, Cm, Al, Dl,
                                                     yhi, ylo);
        // o = (y*gate) @ W_out^T : [4096, 768], K=1536
        gemm_split<<<dim3(NTOK / 128, D_MODEL / 128), 256, GEMM_SMEM>>>(
            yhi, ylo, wohi + oWo, wolo + oWo, o, NTOK, D_MODEL, D_INNER,
            0, nullptr, nullptr);
        // x <- x + LN(o + x)  (emit bf16 split x for next layer's GEMMs)
        ln_kernel<<<NTOK, 256>>>(o, x, x, lg, lb, x, xhi, xlo, nullptr);
    }

    // final LN (emit fp16 x for logits GEMM)
    ln_kernel<<<NTOK, 256>>>(x, nullptr, nullptr, fin_g, fin_b, x,
                             nullptr, nullptr, xf16);
    // logits = x @ emb^T : [4096, 32000]  (plain fp16)
    gemm_fp16_plain<<<dim3(NTOK / 128, VOCAB / 128), 256, GEMM16_SMEM>>>(
        xf16, ef16, logits, NTOK, VOCAB, D_MODEL);
}

// round 13
// speedup vs baseline: 1.2276x; 1.2276x over previous
#include <cuda_runtime.h>
#include <cuda_bf16.h>
#include <cuda_fp16.h>
#include <math.h>
#include <stdint.h>

// ---------------- problem constants ----------------
#define D_MODEL  768
#define N_LAYERS 2
#define D_STATE  16
#define VOCAB    32000
#define D_INNER  1536            // 2*D_MODEL
#define BATCH    2
#define SEQ      2048
#define NTOK     (BATCH*SEQ)     // 4096
#define LN_EPS   1e-5f

// ---------------- scratch (device globals; no mallocs allowed) ----------------
__device__ static float g_x [NTOK * D_MODEL];
__device__ static float g_xp[NTOK * 2 * D_INNER];
__device__ static float g_dt[NTOK * D_INNER];
__device__ static float g_Bm[NTOK * D_STATE];
__device__ static float g_Cm[NTOK * D_STATE];
__device__ static float g_y [NTOK * D_INNER];
__device__ static float g_o [NTOK * D_MODEL];
// bf16 split operands (layer GEMMs, 3-term)
__device__ static __nv_bfloat16 g_xhi[NTOK * D_MODEL];
__device__ static __nv_bfloat16 g_xlo[NTOK * D_MODEL];
__device__ static __nv_bfloat16 g_yhi[NTOK * D_INNER];
__device__ static __nv_bfloat16 g_ylo[NTOK * D_INNER];
__device__ static __nv_bfloat16 g_wihi[N_LAYERS * 2 * D_INNER * D_MODEL];
__device__ static __nv_bfloat16 g_wilo[N_LAYERS * 2 * D_INNER * D_MODEL];
__device__ static __nv_bfloat16 g_wdhi[N_LAYERS * D_INNER * D_MODEL];
__device__ static __nv_bfloat16 g_wdlo[N_LAYERS * D_INNER * D_MODEL];
__device__ static __nv_bfloat16 g_wohi[N_LAYERS * D_MODEL * D_INNER];
__device__ static __nv_bfloat16 g_wolo[N_LAYERS * D_MODEL * D_INNER];
// fp16 operands (logits GEMM, plain fp16 x fp16)
__device__ static __half g_xf16[NTOK * D_MODEL];
__device__ static __half g_ef16[VOCAB * D_MODEL];

// ======================= helpers =======================
#define SW128X(o) ((o) ^ (((o) >> 3) & 0x70))

__device__ __forceinline__ uint32_t s2u(const void* p) {
    uint32_t a;
    asm("{ .reg .u64 t; cvta.to.shared.u64 t, %1; cvt.u32.u64 %0, t; }"
        : "=r"(a) : "l"(p));
    return a;
}

__device__ __forceinline__ void ldsm4(uint32_t* r, uint32_t addr) {
    asm volatile("ldmatrix.sync.aligned.m8n8.x4.shared.b16 {%0,%1,%2,%3}, [%4];"
                 : "=r"(r[0]), "=r"(r[1]), "=r"(r[2]), "=r"(r[3]) : "r"(addr));
}

__device__ __forceinline__ void mma_bf16(float* c, const uint32_t* a,
                                         uint32_t b0, uint32_t b1) {
    asm volatile(
        "mma.sync.aligned.m16n8k16.row.col.f32.bf16.bf16.f32 "
        "{%0,%1,%2,%3}, {%4,%5,%6,%7}, {%8,%9}, {%0,%1,%2,%3};"
        : "+f"(c[0]), "+f"(c[1]), "+f"(c[2]), "+f"(c[3])
        : "r"(a[0]), "r"(a[1]), "r"(a[2]), "r"(a[3]), "r"(b0), "r"(b1));
}

__device__ __forceinline__ void mma_fp16(float* c, const uint32_t* a,
                                         uint32_t b0, uint32_t b1) {
    asm volatile(
        "mma.sync.aligned.m16n8k16.row.col.f32.f16.f16.f32 "
        "{%0,%1,%2,%3}, {%4,%5,%6,%7}, {%8,%9}, {%0,%1,%2,%3};"
        : "+f"(c[0]), "+f"(c[1]), "+f"(c[2]), "+f"(c[3])
        : "r"(a[0]), "r"(a[1]), "r"(a[2]), "r"(a[3]), "r"(b0), "r"(b1));
}

__device__ __forceinline__ void cp16(uint32_t saddr, const void* gaddr) {
    asm volatile("cp.async.ca.shared.global [%0], [%1], 16;"
                 :: "r"(saddr), "l"(gaddr) : "memory");
}

__device__ __forceinline__ uint32_t pack_bf2(float a, float b) {
    __nv_bfloat162 t = __floats2bfloat162_rn(a, b);
    return *(uint32_t*)&t;
}
__device__ __forceinline__ uint32_t pack_hf2(float a, float b) {
    __half2 t = __floats2half2_rn(a, b);
    return *(uint32_t*)&t;
}

// =================== split-bf16 tensor GEMM: C = A @ B^T (3-term) ===========
// Proven config: tile 128x128, K-chunk 64, single 64KB stage, 2 CTAs/SM.
#define OPA_H 0
#define OPA_L 16384
#define OPB_H 32768
#define OPB_L 49152
#define GEMM_SMEM 65536

__global__ void __launch_bounds__(256, 2)
gemm_split(const __nv_bfloat16* __restrict__ Ahi, const __nv_bfloat16* __restrict__ Alo,
           const __nv_bfloat16* __restrict__ Bhi, const __nv_bfloat16* __restrict__ Blo,
           float* __restrict__ C, int M, int N, int K,
           int mode, const float* __restrict__ eb1, const float* __restrict__ eb2) {
    extern __shared__ char smc[];
    const uint32_t sb = s2u(smc);
    const int tid = threadIdx.x;
    const int wid = tid >> 5, lid = tid & 31;
    const int wm = wid & 1, wn = wid >> 1;          // warp grid 2(M) x 4(N)
    const int bm = blockIdx.x * 128, bn = blockIdx.y * 128;

    const int rin = lid & 7;
    const uint32_t xr = (uint32_t)rin << 4;
    const int amat = lid >> 3;
    const uint32_t aKq = (uint32_t)(amat >> 1) * 16;
    uint32_t aRow[4];
#pragma unroll
    for (int mt = 0; mt < 4; mt++)
        aRow[mt] = (uint32_t)(wm * 64 + mt * 16 + (amat & 1) * 8 + rin) * 128;
    const int bpair = lid >> 4, bsub = (lid >> 3) & 1;
    const uint32_t bKq = (uint32_t)bsub * 16;
    uint32_t bRow[2];
#pragma unroll
    for (int p = 0; p < 2; p++)
        bRow[p] = (uint32_t)(wn * 32 + p * 16 + bpair * 8 + rin) * 128;

    const int grow = tid >> 1;
    const int gch0 = (tid & 1) * 4;
    uint32_t sOff[4];
#pragma unroll
    for (int j = 0; j < 4; j++)
        sOff[j] = SW128X((uint32_t)grow * 128 + (uint32_t)(gch0 + j) * 16);

    const __nv_bfloat16* gAh = Ahi + (size_t)(bm + grow) * K + gch0 * 8;
    const __nv_bfloat16* gAl = Alo + (size_t)(bm + grow) * K + gch0 * 8;
    const __nv_bfloat16* gBh = Bhi + (size_t)(bn + grow) * K + gch0 * 8;
    const __nv_bfloat16* gBl = Blo + (size_t)(bn + grow) * K + gch0 * 8;

    float acc[4][4][4];
#pragma unroll
    for (int mt = 0; mt < 4; mt++)
#pragma unroll
        for (int nt = 0; nt < 4; nt++)
#pragma unroll
            for (int i = 0; i < 4; i++) acc[mt][nt][i] = 0.f;

    const int NC = K / 64;
    for (int c = 0; c < NC; c++) {
        const int k0 = c * 64;
        __syncthreads();
#pragma unroll
        for (int j = 0; j < 4; j++) {
            cp16(sb + OPA_H + sOff[j], gAh + k0 + j * 8);
            cp16(sb + OPA_L + sOff[j], gAl + k0 + j * 8);
            cp16(sb + OPB_H + sOff[j], gBh + k0 + j * 8);
            cp16(sb + OPB_L + sOff[j], gBl + k0 + j * 8);
        }
        asm volatile("cp.async.commit_group;" ::: "memory");
        asm volatile("cp.async.wait_group 0;" ::: "memory");
        __syncthreads();

#pragma unroll
        for (int ks = 0; ks < 4; ks++) {
            const uint32_t aoff = (((uint32_t)ks * 32 + aKq) ^ xr);
            const uint32_t boff = (((uint32_t)ks * 32 + bKq) ^ xr);
            uint32_t ah[4][4], bb[2][4];
#pragma unroll
            for (int mt = 0; mt < 4; mt++)
                ldsm4(ah[mt], sb + OPA_H + aRow[mt] + aoff);
#pragma unroll
            for (int p = 0; p < 2; p++)
                ldsm4(bb[p], sb + OPB_H + bRow[p] + boff);
#pragma unroll
            for (int mt = 0; mt < 4; mt++)
#pragma unroll
                for (int nt = 0; nt < 4; nt++)
                    mma_bf16(acc[mt][nt], ah[mt],
                             bb[nt >> 1][(nt & 1) * 2], bb[nt >> 1][(nt & 1) * 2 + 1]);
#pragma unroll
            for (int p = 0; p < 2; p++)
                ldsm4(bb[p], sb + OPB_L + bRow[p] + boff);
#pragma unroll
            for (int mt = 0; mt < 4; mt++)
#pragma unroll
                for (int nt = 0; nt < 4; nt++)
                    mma_bf16(acc[mt][nt], ah[mt],
                             bb[nt >> 1][(nt & 1) * 2], bb[nt >> 1][(nt & 1) * 2 + 1]);
#pragma unroll
            for (int mt = 0; mt < 4; mt++)
                ldsm4(ah[mt], sb + OPA_L + aRow[mt] + aoff);
#pragma unroll
            for (int p = 0; p < 2; p++)
                ldsm4(bb[p], sb + OPB_H + bRow[p] + boff);
#pragma unroll
            for (int mt = 0; mt < 4; mt++)
#pragma unroll
                for (int nt = 0; nt < 4; nt++)
                    mma_bf16(acc[mt][nt], ah[mt],
                             bb[nt >> 1][(nt & 1) * 2], bb[nt >> 1][(nt & 1) * 2 + 1]);
        }
    }

    const int gid = lid >> 2, tig = lid & 3;
#pragma unroll
    for (int mt = 0; mt < 4; mt++) {
#pragma unroll
        for (int nt = 0; nt < 4; nt++) {
            int r0 = bm + wm * 64 + mt * 16 + gid;
            int c0 = bn + wn * 32 + nt * 8 + tig * 2;
            float v[4] = {acc[mt][nt][0], acc[mt][nt][1],
                          acc[mt][nt][2], acc[mt][nt][3]};
            if (mode == 1) {
                float bb0 = eb1[c0] + eb2[c0];
                float bb1 = eb1[c0 + 1] + eb2[c0 + 1];
#pragma unroll
                for (int i = 0; i < 4; i++) {
                    float t = v[i] + ((i & 1) ? bb1 : bb0);
                    float sp = (t > 20.f) ? t : log1pf(expf(t));
                    v[i] = fminf(fmaxf(sp, 0.f), 1.f);
                }
            }
            *(float2*)&C[(size_t)r0 * N + c0]       = make_float2(v[0], v[1]);
            *(float2*)&C[(size_t)(r0 + 8) * N + c0] = make_float2(v[2], v[3]);
        }
    }
}

// ============ plain fp16 GEMM: C = A @ B^T (logits only) ==============
#define FP_A  0
#define FP_B  16384
#define GEMM16_SMEM 32768

__global__ void __launch_bounds__(256, 2)
gemm_fp16_plain(const __half* __restrict__ A, const __half* __restrict__ B,
                float* __restrict__ C, int M, int N, int K) {
    extern __shared__ char smc[];
    const uint32_t sb = s2u(smc);
    const int tid = threadIdx.x;
    const int wid = tid >> 5, lid = tid & 31;
    const int wm = wid & 1, wn = wid >> 1;
    const int bm = blockIdx.x * 128, bn = blockIdx.y * 128;

    const int rin = lid & 7;
    const uint32_t xr = (uint32_t)rin << 4;
    const int amat = lid >> 3;
    const uint32_t aKq = (uint32_t)(amat >> 1) * 16;
    uint32_t aRow[4];
#pragma unroll
    for (int mt = 0; mt < 4; mt++)
        aRow[mt] = (uint32_t)(wm * 64 + mt * 16 + (amat & 1) * 8 + rin) * 128;
    const int bpair = lid >> 4, bsub = (lid >> 3) & 1;
    const uint32_t bKq = (uint32_t)bsub * 16;
    uint32_t bRow[2];
#pragma unroll
    for (int p = 0; p < 2; p++)
        bRow[p] = (uint32_t)(wn * 32 + p * 16 + bpair * 8 + rin) * 128;

    const int grow = tid >> 1;
    const int gch0 = (tid & 1) * 4;
    uint32_t sOff[4];
#pragma unroll
    for (int j = 0; j < 4; j++)
        sOff[j] = SW128X((uint32_t)grow * 128 + (uint32_t)(gch0 + j) * 16);

    const __half* gA = A + (size_t)(bm + grow) * K + gch0 * 8;
    const __half* gB = B + (size_t)(bn + grow) * K + gch0 * 8;

    float acc[4][4][4];
#pragma unroll
    for (int mt = 0; mt < 4; mt++)
#pragma unroll
        for (int nt = 0; nt < 4; nt++)
#pragma unroll
            for (int i = 0; i < 4; i++) acc[mt][nt][i] = 0.f;

    const int NC = K / 64;
    for (int c = 0; c < NC; c++) {
        const int k0 = c * 64;
        __syncthreads();
#pragma unroll
        for (int j = 0; j < 4; j++) {
            cp16(sb + FP_A + sOff[j], gA + k0 + j * 8);
            cp16(sb + FP_B + sOff[j], gB + k0 + j * 8);
        }
        asm volatile("cp.async.commit_group;" ::: "memory");
        asm volatile("cp.async.wait_group 0;" ::: "memory");
        __syncthreads();

#pragma unroll
        for (int ks = 0; ks < 4; ks++) {
            const uint32_t aoff = (((uint32_t)ks * 32 + aKq) ^ xr);
            const uint32_t boff = (((uint32_t)ks * 32 + bKq) ^ xr);
            uint32_t ah[4][4], bb[2][4];
#pragma unroll
            for (int mt = 0; mt < 4; mt++)
                ldsm4(ah[mt], sb + FP_A + aRow[mt] + aoff);
#pragma unroll
            for (int p = 0; p < 2; p++)
                ldsm4(bb[p], sb + FP_B + bRow[p] + boff);
#pragma unroll
            for (int mt = 0; mt < 4; mt++)
#pragma unroll
                for (int nt = 0; nt < 4; nt++)
                    mma_fp16(acc[mt][nt], ah[mt],
                             bb[nt >> 1][(nt & 1) * 2], bb[nt >> 1][(nt & 1) * 2 + 1]);
        }
    }

    const int gid = lid >> 2, tig = lid & 3;
#pragma unroll
    for (int mt = 0; mt < 4; mt++) {
#pragma unroll
        for (int nt = 0; nt < 4; nt++) {
            int r0 = bm + wm * 64 + mt * 16 + gid;
            int c0 = bn + wn * 32 + nt * 8 + tig * 2;
            *(float2*)&C[(size_t)r0 * N + c0] =
                make_float2(acc[mt][nt][0], acc[mt][nt][1]);
            *(float2*)&C[(size_t)(r0 + 8) * N + c0] =
                make_float2(acc[mt][nt][2], acc[mt][nt][3]);
        }
    }
}

// ------------- vectorized fp32 -> (hi, lo) bf16 split (4 elems/thread) -------------
__global__ void split_kernel(const float* __restrict__ src,
                             __nv_bfloat16* __restrict__ hi,
                             __nv_bfloat16* __restrict__ lo, int n4) {
    int i = blockIdx.x * 256 + threadIdx.x;
    if (i < n4) {
        float4 v = ((const float4*)src)[i];
        float a[4] = {v.x, v.y, v.z, v.w};
        float hf[4], lf[4];
#pragma unroll
        for (int j = 0; j < 4; j++) {
            __nv_bfloat16 h = __float2bfloat16(a[j]);
            hf[j] = __bfloat162float(h);
            lf[j] = a[j] - hf[j];
        }
        ((uint2*)hi)[i] = make_uint2(pack_bf2(hf[0], hf[1]), pack_bf2(hf[2], hf[3]));
        ((uint2*)lo)[i] = make_uint2(pack_bf2(lf[0], lf[1]), pack_bf2(lf[2], lf[3]));
    }
}

// ------------- vectorized fp32 -> fp16 convert ----------------
__global__ void conv_fp16_kernel(const float* __restrict__ src,
                                 __half* __restrict__ dst, int n4) {
    int i = blockIdx.x * 256 + threadIdx.x;
    if (i < n4) {
        float4 v = ((const float4*)src)[i];
        ((uint2*)dst)[i] = make_uint2(pack_hf2(v.x, v.y), pack_hf2(v.z, v.w));
    }
}

// ---------------- embedding gather (+ bf16 split emit) ----------------
__global__ void embed_kernel(const int* __restrict__ ids,
                             const float* __restrict__ emb,
                             float* __restrict__ x,
                             __nv_bfloat16* __restrict__ xhi,
                             __nv_bfloat16* __restrict__ xlo) {
    int row = blockIdx.x;
    int id  = ids[row];
    float4 v = ((const float4*)(emb + (size_t)id * D_MODEL))[threadIdx.x];
    size_t base = (size_t)row * D_MODEL + threadIdx.x * 4;
    ((float4*)(x + (size_t)row * D_MODEL))[threadIdx.x] = v;
    float a[4] = {v.x, v.y, v.z, v.w};
#pragma unroll
    for (int j = 0; j < 4; j++) {
        __nv_bfloat16 h = __float2bfloat16(a[j]);
        xhi[base + j] = h;
        xlo[base + j] = __float2bfloat16(a[j] - __bfloat162float(h));
    }
}

// ---------------- skinny GEMM for B/C projections (N=16 each) ----------------
__global__ __launch_bounds__(256)
void bc_gemm(const float* __restrict__ x, const float* __restrict__ Wb,
             const float* __restrict__ Wc, float* __restrict__ Bm,
             float* __restrict__ Cm) {
    __shared__ float xs[8][D_MODEL];
    int row0 = blockIdx.x * 8;
    const float4* xg = (const float4*)(x + (size_t)row0 * D_MODEL);
    float4* xsv = (float4*)xs;
    for (int i = threadIdx.x; i < 8 * D_MODEL / 4; i += 256) xsv[i] = xg[i];
    __syncthreads();

    int r = threadIdx.x >> 5;
    int c = threadIdx.x & 31;
    const float* W = (c < 16) ? (Wb + (size_t)c * D_MODEL)
                              : (Wc + (size_t)(c - 16) * D_MODEL);
    const float4* Wv = (const float4*)W;
    const float4* xr = (const float4*)xs[r];
    float s = 0.f;
#pragma unroll 4
    for (int k = 0; k < D_MODEL / 4; k++) {
        float4 w = Wv[k], v = xr[k];
        s += w.x * v.x + w.y * v.y + w.z * v.z + w.w * v.w;
    }
    if (c < 16) Bm[(size_t)(row0 + r) * D_STATE + c]        = s;
    else        Cm[(size_t)(row0 + r) * D_STATE + (c - 16)] = s;
}

// ======== SSM scan: round-11 proven TCH=32 double-buffered version ========
#define TCH 32
__global__ __launch_bounds__(128)
void ssm_scan(const float* __restrict__ xp, const float* __restrict__ dtc,
              const float* __restrict__ Bm, const float* __restrict__ Cm,
              const float* __restrict__ Amat, const float* __restrict__ Dvec,
              float* __restrict__ yout) {
    __shared__ float  xp_s[2][TCH][64];
    __shared__ float  dt_s[2][TCH][64];
    __shared__ float4 B_s [2][TCH][4];
    __shared__ float4 C_s [2][TCH][4];

    const int tid = threadIdx.x;
    const int wid = tid >> 5, lid = tid & 31;
    const int ch   = wid * 16 + (lid & 15);      // 0..63 local channel
    const int half = lid >> 4;                   // states [0,8) or [8,16)
    const int d0 = blockIdx.x * 64;
    const int d  = d0 + ch;
    const int b  = blockIdx.y;

    float Ar[8], h[8];
#pragma unroll
    for (int j = 0; j < 8; j++) {
        Ar[j] = Amat[(size_t)d * D_STATE + half * 8 + j];
        h[j]  = 0.f;
    }
    const float Dd = Dvec[d];

    const int tt0 = tid >> 4;            // 0..7
    const int seg = (tid & 15) * 4;      // float offset within 64-ch row

    auto issue_chunk = [&](int buf, int tc) {
#pragma unroll
        for (int r = 0; r < 4; r++) {
            int tt = tt0 + r * 8;
            size_t row = (size_t)b * SEQ + tc + tt;
            cp16(s2u(&xp_s[buf][tt][seg]), xp  + row * (2 * D_INNER) + d0 + seg);
            cp16(s2u(&dt_s[buf][tt][seg]), dtc + row * D_INNER       + d0 + seg);
        }
        size_t bcbase = ((size_t)b * SEQ + tc) * D_STATE;   // 512 floats / chunk
        cp16(s2u((float*)B_s[buf] + tid * 4), Bm + bcbase + tid * 4);
        cp16(s2u((float*)C_s[buf] + tid * 4), Cm + bcbase + tid * 4);
        asm volatile("cp.async.commit_group;" ::: "memory");
    };

    issue_chunk(0, 0);
    const int NCH = SEQ / TCH;
    for (int c = 0; c < NCH; c++) {
        const int buf = c & 1;
        if (c + 1 < NCH) {
            issue_chunk(buf ^ 1, (c + 1) * TCH);
            asm volatile("cp.async.wait_group 1;" ::: "memory");
        } else {
            asm volatile("cp.async.wait_group 0;" ::: "memory");
        }
        __syncthreads();

        const int tcg = c * TCH;
#pragma unroll 4
        for (int tt = 0; tt < TCH; tt++) {
            float u  = xp_s[buf][tt][ch];
            float dv = dt_s[buf][tt][ch];
            float4 Bv0 = B_s[buf][tt][half * 2];
            float4 Bv1 = B_s[buf][tt][half * 2 + 1];
            float4 Cv0 = C_s[buf][tt][half * 2];
            float4 Cv1 = C_s[buf][tt][half * 2 + 1];
            float bs[8] = {Bv0.x, Bv0.y, Bv0.z, Bv0.w, Bv1.x, Bv1.y, Bv1.z, Bv1.w};
            float cs[8] = {Cv0.x, Cv0.y, Cv0.z, Cv0.w, Cv1.x, Cv1.y, Cv1.z, Cv1.w};
            float u01 = 0.1f * u;
            float adt = 0.1f * dv;
            float p0 = 0.f, p1 = 0.f;
#pragma unroll
            for (int j = 0; j < 8; j++) {
                float hv = h[j];
                hv = fmaf(hv * Ar[j], adt, fmaf(bs[j], u01, hv));
                h[j] = hv;
                float p = hv * cs[j];
                if (j & 1) p1 += p; else p0 += p;
            }
            float part = p0 + p1;
            float tot = part + __shfl_xor_sync(0xffffffffu, part, 16);
            if (!half)
                yout[((size_t)b * SEQ + tcg + tt) * D_INNER + d] = Dd * u + tot;
        }
        __syncthreads();
    }
}

// ---------------- gate multiply -> split bf16 y (4 elems/thread) ----------------
__global__ void gate_mul(const float* __restrict__ y, const float* __restrict__ xp,
                         __nv_bfloat16* __restrict__ yhi,
                         __nv_bfloat16* __restrict__ ylo) {
    int i = blockIdx.x * 256 + threadIdx.x;        // quad index
    int row = i / (D_INNER / 4);
    int dq  = i - row * (D_INNER / 4);
    float4 yv = ((const float4*)y)[i];
    const float4 gv = *(const float4*)&xp[(size_t)row * (2 * D_INNER) + D_INNER + dq * 4];
    float ya[4] = {yv.x, yv.y, yv.z, yv.w};
    float ga[4] = {gv.x, gv.y, gv.z, gv.w};
    float hf[4], lf[4];
#pragma unroll
    for (int j = 0; j < 4; j++) {
        float v = ya[j] * (1.f / (1.f + expf(-ga[j])));
        __nv_bfloat16 hb = __float2bfloat16(v);
        hf[j] = __bfloat162float(hb);
        lf[j] = v - hf[j];
    }
    ((uint2*)yhi)[i] = make_uint2(pack_bf2(hf[0], hf[1]), pack_bf2(hf[2], hf[3]));
    ((uint2*)ylo)[i] = make_uint2(pack_bf2(lf[0], lf[1]), pack_bf2(lf[2], lf[3]));
}

// -------- layernorm: out = post? + LN(in + res?) * g + b (+ bf16/fp16 emit) --------
__device__ __forceinline__ float block_reduce(float v, float* red) {
    for (int o = 16; o > 0; o >>= 1) v += __shfl_down_sync(0xffffffffu, v, o);
    if ((threadIdx.x & 31) == 0) red[threadIdx.x >> 5] = v;
    __syncthreads();
    float t = 0.f;
#pragma unroll
    for (int w = 0; w < 8; w++) t += red[w];
    return t;
}

__global__ __launch_bounds__(256)
void ln_kernel(const float* __restrict__ in, const float* __restrict__ res,
               const float* __restrict__ post,
               const float* __restrict__ g, const float* __restrict__ b,
               float* __restrict__ out,
               __nv_bfloat16* __restrict__ ohi, __nv_bfloat16* __restrict__ olo,
               __half* __restrict__ of16) {
    __shared__ float red[8];
    const int row = blockIdx.x;
    const int t   = threadIdx.x;
    float v[3], pv[3];
    float s = 0.f;
#pragma unroll
    for (int i = 0; i < 3; i++) {
        int c = t + i * 256;
        float x = in[(size_t)row * D_MODEL + c];
        if (res) x += res[(size_t)row * D_MODEL + c];
        pv[i] = post ? post[(size_t)row * D_MODEL + c] : 0.f;
        v[i] = x;
        s += x;
    }
    float tot = block_reduce(s, red);
    float mu = tot * (1.f / D_MODEL);
    __syncthreads();
    float q = 0.f;
#pragma unroll
    for (int i = 0; i < 3; i++) {
        float dd = v[i] - mu;
        q += dd * dd;
    }
    float qtot = block_reduce(q, red);
    float rs = rsqrtf(qtot * (1.f / D_MODEL) + LN_EPS);
#pragma unroll
    for (int i = 0; i < 3; i++) {
        int c = t + i * 256;
        float o = pv[i] + (v[i] - mu) * rs * g[c] + b[c];
        size_t idx = (size_t)row * D_MODEL + c;
        out[idx] = o;
        if (ohi) {
            __nv_bfloat16 h = __float2bfloat16(o);
            ohi[idx] = h;
            olo[idx] = __float2bfloat16(o - __bfloat162float(h));
        }
        if (of16) of16[idx] = __float2half(o);
    }
}

// ---------------- launch ----------------
extern "C" void kernel_launch(void* const* d_in, const int* in_sizes, int n_in,
                              void* d_out, int out_size) {
    const int*   input_ids = (const int*)  d_in[0];
    const float* emb       = (const float*)d_in[1];
    const float* W_in      = (const float*)d_in[2];   // [2, 3072, 768]
    const float* W_dt      = (const float*)d_in[3];   // [2, 1536, 768]
    const float* b_dt      = (const float*)d_in[4];
    const float* dt_bias   = (const float*)d_in[5];
    const float* W_B       = (const float*)d_in[6];
    const float* W_C       = (const float*)d_in[7];
    const float* Amat      = (const float*)d_in[8];
    const float* Dvec      = (const float*)d_in[9];
    const float* W_out     = (const float*)d_in[10];  // [2, 768, 1536]
    const float* ln_g      = (const float*)d_in[11];
    const float* ln_b      = (const float*)d_in[12];
    const float* fin_g     = (const float*)d_in[13];
    const float* fin_b     = (const float*)d_in[14];
    float* logits = (float*)d_out;                    // [4096, 32000]

    float *x, *xp, *dt, *Bm, *Cm, *y, *o;
    __nv_bfloat16 *xhi, *xlo, *yhi, *ylo;
    __nv_bfloat16 *wihi, *wilo, *wdhi, *wdlo, *wohi, *wolo;
    __half *xf16, *ef16;
    cudaGetSymbolAddress((void**)&x,  g_x);
    cudaGetSymbolAddress((void**)&xp, g_xp);
    cudaGetSymbolAddress((void**)&dt, g_dt);
    cudaGetSymbolAddress((void**)&Bm, g_Bm);
    cudaGetSymbolAddress((void**)&Cm, g_Cm);
    cudaGetSymbolAddress((void**)&y,  g_y);
    cudaGetSymbolAddress((void**)&o,  g_o);
    cudaGetSymbolAddress((void**)&xhi, g_xhi);
    cudaGetSymbolAddress((void**)&xlo, g_xlo);
    cudaGetSymbolAddress((void**)&yhi, g_yhi);
    cudaGetSymbolAddress((void**)&ylo, g_ylo);
    cudaGetSymbolAddress((void**)&wihi, g_wihi);
    cudaGetSymbolAddress((void**)&wilo, g_wilo);
    cudaGetSymbolAddress((void**)&wdhi, g_wdhi);
    cudaGetSymbolAddress((void**)&wdlo, g_wdlo);
    cudaGetSymbolAddress((void**)&wohi, g_wohi);
    cudaGetSymbolAddress((void**)&wolo, g_wolo);
    cudaGetSymbolAddress((void**)&xf16, g_xf16);
    cudaGetSymbolAddress((void**)&ef16, g_ef16);

    cudaFuncSetAttribute(gemm_split, cudaFuncAttributeMaxDynamicSharedMemorySize,
                         GEMM_SMEM);
    cudaFuncSetAttribute(gemm_fp16_plain, cudaFuncAttributeMaxDynamicSharedMemorySize,
                         GEMM16_SMEM);

    embed_kernel<<<NTOK, D_MODEL / 4>>>(input_ids, emb, x, xhi, xlo);

    // hoisted weight/emb splits (vectorized, dedicated buffers)
    {
        int n4 = N_LAYERS * 2 * D_INNER * D_MODEL / 4;
        split_kernel<<<(n4 + 255) / 256, 256>>>(W_in, wihi, wilo, n4);
        n4 = N_LAYERS * D_INNER * D_MODEL / 4;
        split_kernel<<<(n4 + 255) / 256, 256>>>(W_dt, wdhi, wdlo, n4);
        n4 = N_LAYERS * D_MODEL * D_INNER / 4;
        split_kernel<<<(n4 + 255) / 256, 256>>>(W_out, wohi, wolo, n4);
        n4 = VOCAB * D_MODEL / 4;
        conv_fp16_kernel<<<(n4 + 255) / 256, 256>>>(emb, ef16, n4);
    }

    for (int l = 0; l < N_LAYERS; l++) {
        const size_t oWi = (size_t)l * 2 * D_INNER * D_MODEL;
        const size_t oWd = (size_t)l * D_INNER * D_MODEL;
        const size_t oWo = (size_t)l * D_MODEL * D_INNER;
        const float* bd = b_dt    + (size_t)l * D_INNER;
        const float* db = dt_bias + (size_t)l * D_INNER;
        const float* Wb = W_B   + (size_t)l * D_STATE * D_MODEL;
        const float* Wc = W_C   + (size_t)l * D_STATE * D_MODEL;
        const float* Al = Amat  + (size_t)l * D_INNER * D_STATE;
        const float* Dl = Dvec  + (size_t)l * D_INNER;
        const float* lg = ln_g  + (size_t)l * D_MODEL;
        const float* lb = ln_b  + (size_t)l * D_MODEL;

        // xp = x @ W_in^T : [4096, 3072]
        gemm_split<<<dim3(NTOK / 128, 2 * D_INNER / 128), 256, GEMM_SMEM>>>(
            xhi, xlo, wihi + oWi, wilo + oWi, xp, NTOK, 2 * D_INNER, D_MODEL,
            0, nullptr, nullptr);
        // dt = softplus/clip(x @ W_dt^T + biases) fused in epilogue
        gemm_split<<<dim3(NTOK / 128, D_INNER / 128), 256, GEMM_SMEM>>>(
            xhi, xlo, wdhi + oWd, wdlo + oWd, dt, NTOK, D_INNER, D_MODEL,
            1, bd, db);
        bc_gemm<<<NTOK / 8, 256>>>(x, Wb, Wc, Bm, Cm);
        ssm_scan<<<dim3(D_INNER / 64, BATCH), 128>>>(xp, dt, Bm, Cm, Al, Dl, y);
        gate_mul<<<NTOK * D_INNER / 4 / 256, 256>>>(y, xp, yhi, ylo);
        // o = (y*gate) @ W_out^T : [4096, 768], K=1536
        gemm_split<<<dim3(NTOK / 128, D_MODEL / 128), 256, GEMM_SMEM>>>(
            yhi, ylo, wohi + oWo, wolo + oWo, o, NTOK, D_MODEL, D_INNER,
            0, nullptr, nullptr);
        // x <- x + LN(o + x)  (emit bf16 split x for next layer's GEMMs)
        ln_kernel<<<NTOK, 256>>>(o, x, x, lg, lb, x, xhi, xlo, nullptr);
    }

    // final LN (emit fp16 x for logits GEMM)
    ln_kernel<<<NTOK, 256>>>(x, nullptr, nullptr, fin_g, fin_b, x,
                             nullptr, nullptr, xf16);
    // logits = x @ emb^T : [4096, 32000]  (plain fp16)
    gemm_fp16_plain<<<dim3(NTOK / 128, VOCAB / 128), 256, GEMM16_SMEM>>>(
        xf16, ef16, logits, NTOK, VOCAB, D_MODEL);
}

// round 14
// speedup vs baseline: 1.3171x; 1.0728x over previous
#include <cuda_runtime.h>
#include <cuda_bf16.h>
#include <cuda_fp16.h>
#include <math.h>
#include <stdint.h>

// ---------------- problem constants ----------------
#define D_MODEL  768
#define N_LAYERS 2
#define D_STATE  16
#define VOCAB    32000
#define D_INNER  1536            // 2*D_MODEL
#define BATCH    2
#define SEQ      2048
#define NTOK     (BATCH*SEQ)     // 4096
#define LN_EPS   1e-5f
#define NCOMB    4608            // [x_ssm | gate | dt] combined width
#define SPLIT_COL 3072           // softplus region starts here

// ---------------- scratch ----------------
__device__ static float g_x  [NTOK * D_MODEL];
__device__ static float g_xpc[NTOK * NCOMB];     // combined xp|gate|dt
__device__ static float g_Bm [NTOK * D_STATE];
__device__ static float g_Cm [NTOK * D_STATE];
__device__ static float g_y  [NTOK * D_INNER];
__device__ static float g_o  [NTOK * D_MODEL];
// bf16 split operands (layer GEMMs, 3-term)
__device__ static __nv_bfloat16 g_xhi[NTOK * D_MODEL];
__device__ static __nv_bfloat16 g_xlo[NTOK * D_MODEL];
__device__ static __nv_bfloat16 g_yhi[NTOK * D_INNER];
__device__ static __nv_bfloat16 g_ylo[NTOK * D_INNER];
__device__ static __nv_bfloat16 g_wchi[N_LAYERS * NCOMB * D_MODEL];   // W_in|W_dt combined
__device__ static __nv_bfloat16 g_wclo[N_LAYERS * NCOMB * D_MODEL];
__device__ static __nv_bfloat16 g_wohi[N_LAYERS * D_MODEL * D_INNER];
__device__ static __nv_bfloat16 g_wolo[N_LAYERS * D_MODEL * D_INNER];
// fp16 operands (logits GEMM)
__device__ static __half g_xf16[NTOK * D_MODEL];
__device__ static __half g_ef16[VOCAB * D_MODEL];

// ======================= helpers =======================
#define SW128X(o) ((o) ^ (((o) >> 3) & 0x70))

__device__ __forceinline__ uint32_t s2u(const void* p) {
    uint32_t a;
    asm("{ .reg .u64 t; cvta.to.shared.u64 t, %1; cvt.u32.u64 %0, t; }"
        : "=r"(a) : "l"(p));
    return a;
}

__device__ __forceinline__ void ldsm4(uint32_t* r, uint32_t addr) {
    asm volatile("ldmatrix.sync.aligned.m8n8.x4.shared.b16 {%0,%1,%2,%3}, [%4];"
                 : "=r"(r[0]), "=r"(r[1]), "=r"(r[2]), "=r"(r[3]) : "r"(addr));
}

__device__ __forceinline__ void mma_bf16(float* c, const uint32_t* a,
                                         uint32_t b0, uint32_t b1) {
    asm volatile(
        "mma.sync.aligned.m16n8k16.row.col.f32.bf16.bf16.f32 "
        "{%0,%1,%2,%3}, {%4,%5,%6,%7}, {%8,%9}, {%0,%1,%2,%3};"
        : "+f"(c[0]), "+f"(c[1]), "+f"(c[2]), "+f"(c[3])
        : "r"(a[0]), "r"(a[1]), "r"(a[2]), "r"(a[3]), "r"(b0), "r"(b1));
}

__device__ __forceinline__ void mma_fp16(float* c, const uint32_t* a,
                                         uint32_t b0, uint32_t b1) {
    asm volatile(
        "mma.sync.aligned.m16n8k16.row.col.f32.f16.f16.f32 "
        "{%0,%1,%2,%3}, {%4,%5,%6,%7}, {%8,%9}, {%0,%1,%2,%3};"
        : "+f"(c[0]), "+f"(c[1]), "+f"(c[2]), "+f"(c[3])
        : "r"(a[0]), "r"(a[1]), "r"(a[2]), "r"(a[3]), "r"(b0), "r"(b1));
}

__device__ __forceinline__ void cp16(uint32_t saddr, const void* gaddr) {
    asm volatile("cp.async.ca.shared.global [%0], [%1], 16;"
                 :: "r"(saddr), "l"(gaddr) : "memory");
}

__device__ __forceinline__ uint32_t pack_bf2(float a, float b) {
    __nv_bfloat162 t = __floats2bfloat162_rn(a, b);
    return *(uint32_t*)&t;
}
__device__ __forceinline__ uint32_t pack_hf2(float a, float b) {
    __half2 t = __floats2half2_rn(a, b);
    return *(uint32_t*)&t;
}

// =================== split-bf16 tensor GEMM: C = A @ B^T (3-term) ===========
// Proven config: tile 128x128, K-chunk 64, single 64KB stage, 2 CTAs/SM.
// mode 1: softplus/clip applied to columns >= SPLIT_COL (biases at c-SPLIT_COL).
#define OPA_H 0
#define OPA_L 16384
#define OPB_H 32768
#define OPB_L 49152
#define GEMM_SMEM 65536

__global__ void __launch_bounds__(256, 2)
gemm_split(const __nv_bfloat16* __restrict__ Ahi, const __nv_bfloat16* __restrict__ Alo,
           const __nv_bfloat16* __restrict__ Bhi, const __nv_bfloat16* __restrict__ Blo,
           float* __restrict__ C, int M, int N, int K,
           int mode, const float* __restrict__ eb1, const float* __restrict__ eb2) {
    extern __shared__ char smc[];
    const uint32_t sb = s2u(smc);
    const int tid = threadIdx.x;
    const int wid = tid >> 5, lid = tid & 31;
    const int wm = wid & 1, wn = wid >> 1;          // warp grid 2(M) x 4(N)
    const int bm = blockIdx.x * 128, bn = blockIdx.y * 128;

    const int rin = lid & 7;
    const uint32_t xr = (uint32_t)rin << 4;
    const int amat = lid >> 3;
    const uint32_t aKq = (uint32_t)(amat >> 1) * 16;
    uint32_t aRow[4];
#pragma unroll
    for (int mt = 0; mt < 4; mt++)
        aRow[mt] = (uint32_t)(wm * 64 + mt * 16 + (amat & 1) * 8 + rin) * 128;
    const int bpair = lid >> 4, bsub = (lid >> 3) & 1;
    const uint32_t bKq = (uint32_t)bsub * 16;
    uint32_t bRow[2];
#pragma unroll
    for (int p = 0; p < 2; p++)
        bRow[p] = (uint32_t)(wn * 32 + p * 16 + bpair * 8 + rin) * 128;

    const int grow = tid >> 1;
    const int gch0 = (tid & 1) * 4;
    uint32_t sOff[4];
#pragma unroll
    for (int j = 0; j < 4; j++)
        sOff[j] = SW128X((uint32_t)grow * 128 + (uint32_t)(gch0 + j) * 16);

    const __nv_bfloat16* gAh = Ahi + (size_t)(bm + grow) * K + gch0 * 8;
    const __nv_bfloat16* gAl = Alo + (size_t)(bm + grow) * K + gch0 * 8;
    const __nv_bfloat16* gBh = Bhi + (size_t)(bn + grow) * K + gch0 * 8;
    const __nv_bfloat16* gBl = Blo + (size_t)(bn + grow) * K + gch0 * 8;

    float acc[4][4][4];
#pragma unroll
    for (int mt = 0; mt < 4; mt++)
#pragma unroll
        for (int nt = 0; nt < 4; nt++)
#pragma unroll
            for (int i = 0; i < 4; i++) acc[mt][nt][i] = 0.f;

    const int NC = K / 64;
    for (int c = 0; c < NC; c++) {
        const int k0 = c * 64;
        __syncthreads();
#pragma unroll
        for (int j = 0; j < 4; j++) {
            cp16(sb + OPA_H + sOff[j], gAh + k0 + j * 8);
            cp16(sb + OPA_L + sOff[j], gAl + k0 + j * 8);
            cp16(sb + OPB_H + sOff[j], gBh + k0 + j * 8);
            cp16(sb + OPB_L + sOff[j], gBl + k0 + j * 8);
        }
        asm volatile("cp.async.commit_group;" ::: "memory");
        asm volatile("cp.async.wait_group 0;" ::: "memory");
        __syncthreads();

#pragma unroll
        for (int ks = 0; ks < 4; ks++) {
            const uint32_t aoff = (((uint32_t)ks * 32 + aKq) ^ xr);
            const uint32_t boff = (((uint32_t)ks * 32 + bKq) ^ xr);
            uint32_t ah[4][4], bb[2][4];
#pragma unroll
            for (int mt = 0; mt < 4; mt++)
                ldsm4(ah[mt], sb + OPA_H + aRow[mt] + aoff);
#pragma unroll
            for (int p = 0; p < 2; p++)
                ldsm4(bb[p], sb + OPB_H + bRow[p] + boff);
#pragma unroll
            for (int mt = 0; mt < 4; mt++)
#pragma unroll
                for (int nt = 0; nt < 4; nt++)
                    mma_bf16(acc[mt][nt], ah[mt],
                             bb[nt >> 1][(nt & 1) * 2], bb[nt >> 1][(nt & 1) * 2 + 1]);
#pragma unroll
            for (int p = 0; p < 2; p++)
                ldsm4(bb[p], sb + OPB_L + bRow[p] + boff);
#pragma unroll
            for (int mt = 0; mt < 4; mt++)
#pragma unroll
                for (int nt = 0; nt < 4; nt++)
                    mma_bf16(acc[mt][nt], ah[mt],
                             bb[nt >> 1][(nt & 1) * 2], bb[nt >> 1][(nt & 1) * 2 + 1]);
#pragma unroll
            for (int mt = 0; mt < 4; mt++)
                ldsm4(ah[mt], sb + OPA_L + aRow[mt] + aoff);
#pragma unroll
            for (int p = 0; p < 2; p++)
                ldsm4(bb[p], sb + OPB_H + bRow[p] + boff);
#pragma unroll
            for (int mt = 0; mt < 4; mt++)
#pragma unroll
                for (int nt = 0; nt < 4; nt++)
                    mma_bf16(acc[mt][nt], ah[mt],
                             bb[nt >> 1][(nt & 1) * 2], bb[nt >> 1][(nt & 1) * 2 + 1]);
        }
    }

    const int gid = lid >> 2, tig = lid & 3;
#pragma unroll
    for (int mt = 0; mt < 4; mt++) {
#pragma unroll
        for (int nt = 0; nt < 4; nt++) {
            int r0 = bm + wm * 64 + mt * 16 + gid;
            int c0 = bn + wn * 32 + nt * 8 + tig * 2;
            float v[4] = {acc[mt][nt][0], acc[mt][nt][1],
                          acc[mt][nt][2], acc[mt][nt][3]};
            if (mode == 1 && c0 >= SPLIT_COL) {
                int cb = c0 - SPLIT_COL;
                float bb0 = eb1[cb] + eb2[cb];
                float bb1 = eb1[cb + 1] + eb2[cb + 1];
#pragma unroll
                for (int i = 0; i < 4; i++) {
                    float t = v[i] + ((i & 1) ? bb1 : bb0);
                    float sp = (t > 20.f) ? t : log1pf(expf(t));
                    v[i] = fminf(fmaxf(sp, 0.f), 1.f);
                }
            }
            *(float2*)&C[(size_t)r0 * N + c0]       = make_float2(v[0], v[1]);
            *(float2*)&C[(size_t)(r0 + 8) * N + c0] = make_float2(v[2], v[3]);
        }
    }
}

// ============ plain fp16 GEMM (logits): 2-stage pipeline, 2 CTAs/SM ==========
#define FP_A   0
#define FP_B   16384
#define FPSTG  32768
#define GEMM16_SMEM (2 * FPSTG)     // 64KB -> still 2 CTAs/SM

__global__ void __launch_bounds__(256, 2)
gemm_fp16_plain(const __half* __restrict__ A, const __half* __restrict__ B,
                float* __restrict__ C, int M, int N, int K) {
    extern __shared__ char smc[];
    const uint32_t sb = s2u(smc);
    const int tid = threadIdx.x;
    const int wid = tid >> 5, lid = tid & 31;
    const int wm = wid & 1, wn = wid >> 1;
    const int bm = blockIdx.x * 128, bn = blockIdx.y * 128;

    const int rin = lid & 7;
    const uint32_t xr = (uint32_t)rin << 4;
    const int amat = lid >> 3;
    const uint32_t aKq = (uint32_t)(amat >> 1) * 16;
    uint32_t aRow[4];
#pragma unroll
    for (int mt = 0; mt < 4; mt++)
        aRow[mt] = (uint32_t)(wm * 64 + mt * 16 + (amat & 1) * 8 + rin) * 128;
    const int bpair = lid >> 4, bsub = (lid >> 3) & 1;
    const uint32_t bKq = (uint32_t)bsub * 16;
    uint32_t bRow[2];
#pragma unroll
    for (int p = 0; p < 2; p++)
        bRow[p] = (uint32_t)(wn * 32 + p * 16 + bpair * 8 + rin) * 128;

    const int grow = tid >> 1;
    const int gch0 = (tid & 1) * 4;
    uint32_t sOff[4];
#pragma unroll
    for (int j = 0; j < 4; j++)
        sOff[j] = SW128X((uint32_t)grow * 128 + (uint32_t)(gch0 + j) * 16);

    const __half* gA = A + (size_t)(bm + grow) * K + gch0 * 8;
    const __half* gB = B + (size_t)(bn + grow) * K + gch0 * 8;

    float acc[4][4][4];
#pragma unroll
    for (int mt = 0; mt < 4; mt++)
#pragma unroll
        for (int nt = 0; nt < 4; nt++)
#pragma unroll
            for (int i = 0; i < 4; i++) acc[mt][nt][i] = 0.f;

    const int NC = K / 64;

    // prologue: chunk 0 -> stage 0
    {
#pragma unroll
        for (int j = 0; j < 4; j++) {
            cp16(sb + FP_A + sOff[j], gA + j * 8);
            cp16(sb + FP_B + sOff[j], gB + j * 8);
        }
        asm volatile("cp.async.commit_group;" ::: "memory");
    }

    for (int c = 0; c < NC; c++) {
        if (c + 1 < NC) {
            const uint32_t st1 = sb + (uint32_t)((c + 1) & 1) * FPSTG;
            const int k1 = (c + 1) * 64;
#pragma unroll
            for (int j = 0; j < 4; j++) {
                cp16(st1 + FP_A + sOff[j], gA + k1 + j * 8);
                cp16(st1 + FP_B + sOff[j], gB + k1 + j * 8);
            }
            asm volatile("cp.async.commit_group;" ::: "memory");
            asm volatile("cp.async.wait_group 1;" ::: "memory");
        } else {
            asm volatile("cp.async.wait_group 0;" ::: "memory");
        }
        __syncthreads();

        const uint32_t st = sb + (uint32_t)(c & 1) * FPSTG;
#pragma unroll
        for (int ks = 0; ks < 4; ks++) {
            const uint32_t aoff = (((uint32_t)ks * 32 + aKq) ^ xr);
            const uint32_t boff = (((uint32_t)ks * 32 + bKq) ^ xr);
            uint32_t ah[4][4], bb[2][4];
#pragma unroll
            for (int mt = 0; mt < 4; mt++)
                ldsm4(ah[mt], st + FP_A + aRow[mt] + aoff);
#pragma unroll
            for (int p = 0; p < 2; p++)
                ldsm4(bb[p], st + FP_B + bRow[p] + boff);
#pragma unroll
            for (int mt = 0; mt < 4; mt++)
#pragma unroll
                for (int nt = 0; nt < 4; nt++)
                    mma_fp16(acc[mt][nt], ah[mt],
                             bb[nt >> 1][(nt & 1) * 2], bb[nt >> 1][(nt & 1) * 2 + 1]);
        }
        __syncthreads();   // stage consumed; next iter may overwrite it
    }

    const int gid = lid >> 2, tig = lid & 3;
#pragma unroll
    for (int mt = 0; mt < 4; mt++) {
#pragma unroll
        for (int nt = 0; nt < 4; nt++) {
            int r0 = bm + wm * 64 + mt * 16 + gid;
            int c0 = bn + wn * 32 + nt * 8 + tig * 2;
            *(float2*)&C[(size_t)r0 * N + c0] =
                make_float2(acc[mt][nt][0], acc[mt][nt][1]);
            *(float2*)&C[(size_t)(r0 + 8) * N + c0] =
                make_float2(acc[mt][nt][2], acc[mt][nt][3]);
        }
    }
}

// ------------- vectorized fp32 -> (hi, lo) bf16 split -------------
__global__ void split_kernel(const float* __restrict__ src,
                             __nv_bfloat16* __restrict__ hi,
                             __nv_bfloat16* __restrict__ lo, int n4) {
    int i = blockIdx.x * 256 + threadIdx.x;
    if (i < n4) {
        float4 v = ((const float4*)src)[i];
        float a[4] = {v.x, v.y, v.z, v.w};
        float hf[4], lf[4];
#pragma unroll
        for (int j = 0; j < 4; j++) {
            __nv_bfloat16 h = __float2bfloat16(a[j]);
            hf[j] = __bfloat162float(h);
            lf[j] = a[j] - hf[j];
        }
        ((uint2*)hi)[i] = make_uint2(pack_bf2(hf[0], hf[1]), pack_bf2(hf[2], hf[3]));
        ((uint2*)lo)[i] = make_uint2(pack_bf2(lf[0], lf[1]), pack_bf2(lf[2], lf[3]));
    }
}

// ------------- vectorized fp32 -> fp16 convert ----------------
__global__ void conv_fp16_kernel(const float* __restrict__ src,
                                 __half* __restrict__ dst, int n4) {
    int i = blockIdx.x * 256 + threadIdx.x;
    if (i < n4) {
        float4 v = ((const float4*)src)[i];
        ((uint2*)dst)[i] = make_uint2(pack_hf2(v.x, v.y), pack_hf2(v.z, v.w));
    }
}

// ---------------- embedding gather (+ bf16 split emit) ----------------
__global__ void embed_kernel(const int* __restrict__ ids,
                             const float* __restrict__ emb,
                             float* __restrict__ x,
                             __nv_bfloat16* __restrict__ xhi,
                             __nv_bfloat16* __restrict__ xlo) {
    int row = blockIdx.x;
    int id  = ids[row];
    float4 v = ((const float4*)(emb + (size_t)id * D_MODEL))[threadIdx.x];
    size_t base = (size_t)row * D_MODEL + threadIdx.x * 4;
    ((float4*)(x + (size_t)row * D_MODEL))[threadIdx.x] = v;
    float a[4] = {v.x, v.y, v.z, v.w};
#pragma unroll
    for (int j = 0; j < 4; j++) {
        __nv_bfloat16 h = __float2bfloat16(a[j]);
        xhi[base + j] = h;
        xlo[base + j] = __float2bfloat16(a[j] - __bfloat162float(h));
    }
}

// ---------------- skinny GEMM for B/C projections (N=16 each) ----------------
__global__ __launch_bounds__(256)
void bc_gemm(const float* __restrict__ x, const float* __restrict__ Wb,
             const float* __restrict__ Wc, float* __restrict__ Bm,
             float* __restrict__ Cm) {
    __shared__ float xs[8][D_MODEL];
    int row0 = blockIdx.x * 8;
    const float4* xg = (const float4*)(x + (size_t)row0 * D_MODEL);
    float4* xsv = (float4*)xs;
    for (int i = threadIdx.x; i < 8 * D_MODEL / 4; i += 256) xsv[i] = xg[i];
    __syncthreads();

    int r = threadIdx.x >> 5;
    int c = threadIdx.x & 31;
    const float* W = (c < 16) ? (Wb + (size_t)c * D_MODEL)
                              : (Wc + (size_t)(c - 16) * D_MODEL);
    const float4* Wv = (const float4*)W;
    const float4* xr = (const float4*)xs[r];
    float s = 0.f;
#pragma unroll 4
    for (int k = 0; k < D_MODEL / 4; k++) {
        float4 w = Wv[k], v = xr[k];
        s += w.x * v.x + w.y * v.y + w.z * v.z + w.w * v.w;
    }
    if (c < 16) Bm[(size_t)(row0 + r) * D_STATE + c]        = s;
    else        Cm[(size_t)(row0 + r) * D_STATE + (c - 16)] = s;
}

// ======== SSM scan: TCH=32 double-buffered (proven); reads combined buffer ========
#define TCH 32
__global__ __launch_bounds__(128)
void ssm_scan(const float* __restrict__ xpc,
              const float* __restrict__ Bm, const float* __restrict__ Cm,
              const float* __restrict__ Amat, const float* __restrict__ Dvec,
              float* __restrict__ yout) {
    __shared__ float  xp_s[2][TCH][64];
    __shared__ float  dt_s[2][TCH][64];
    __shared__ float4 B_s [2][TCH][4];
    __shared__ float4 C_s [2][TCH][4];

    const int tid = threadIdx.x;
    const int wid = tid >> 5, lid = tid & 31;
    const int ch   = wid * 16 + (lid & 15);      // 0..63 local channel
    const int half = lid >> 4;                   // states [0,8) or [8,16)
    const int d0 = blockIdx.x * 64;
    const int d  = d0 + ch;
    const int b  = blockIdx.y;

    float Ar[8], h[8];
#pragma unroll
    for (int j = 0; j < 8; j++) {
        Ar[j] = Amat[(size_t)d * D_STATE + half * 8 + j];
        h[j]  = 0.f;
    }
    const float Dd = Dvec[d];

    const int tt0 = tid >> 4;            // 0..7
    const int seg = (tid & 15) * 4;      // float offset within 64-ch row

    auto issue_chunk = [&](int buf, int tc) {
#pragma unroll
        for (int r = 0; r < 4; r++) {
            int tt = tt0 + r * 8;
            size_t row = (size_t)b * SEQ + tc + tt;
            cp16(s2u(&xp_s[buf][tt][seg]), xpc + row * NCOMB + d0 + seg);
            cp16(s2u(&dt_s[buf][tt][seg]), xpc + row * NCOMB + SPLIT_COL + d0 + seg);
        }
        size_t bcbase = ((size_t)b * SEQ + tc) * D_STATE;
        cp16(s2u((float*)B_s[buf] + tid * 4), Bm + bcbase + tid * 4);
        cp16(s2u((float*)C_s[buf] + tid * 4), Cm + bcbase + tid * 4);
        asm volatile("cp.async.commit_group;" ::: "memory");
    };

    issue_chunk(0, 0);
    const int NCH = SEQ / TCH;
    for (int c = 0; c < NCH; c++) {
        const int buf = c & 1;
        if (c + 1 < NCH) {
            issue_chunk(buf ^ 1, (c + 1) * TCH);
            asm volatile("cp.async.wait_group 1;" ::: "memory");
        } else {
            asm volatile("cp.async.wait_group 0;" ::: "memory");
        }
        __syncthreads();

        const int tcg = c * TCH;
#pragma unroll 4
        for (int tt = 0; tt < TCH; tt++) {
            float u  = xp_s[buf][tt][ch];
            float dv = dt_s[buf][tt][ch];
            float4 Bv0 = B_s[buf][tt][half * 2];
            float4 Bv1 = B_s[buf][tt][half * 2 + 1];
            float4 Cv0 = C_s[buf][tt][half * 2];
            float4 Cv1 = C_s[buf][tt][half * 2 + 1];
            float bs[8] = {Bv0.x, Bv0.y, Bv0.z, Bv0.w, Bv1.x, Bv1.y, Bv1.z, Bv1.w};
            float cs[8] = {Cv0.x, Cv0.y, Cv0.z, Cv0.w, Cv1.x, Cv1.y, Cv1.z, Cv1.w};
            float u01 = 0.1f * u;
            float adt = 0.1f * dv;
            float p0 = 0.f, p1 = 0.f;
#pragma unroll
            for (int j = 0; j < 8; j++) {
                float hv = h[j];
                hv = fmaf(hv * Ar[j], adt, fmaf(bs[j], u01, hv));
                h[j] = hv;
                float p = hv * cs[j];
                if (j & 1) p1 += p; else p0 += p;
            }
            float part = p0 + p1;
            float tot = part + __shfl_xor_sync(0xffffffffu, part, 16);
            if (!half)
                yout[((size_t)b * SEQ + tcg + tt) * D_INNER + d] = Dd * u + tot;
        }
        __syncthreads();
    }
}

// ---------------- gate multiply -> split bf16 y (4 elems/thread) ----------------
__global__ void gate_mul(const float* __restrict__ y, const float* __restrict__ xpc,
                         __nv_bfloat16* __restrict__ yhi,
                         __nv_bfloat16* __restrict__ ylo) {
    int i = blockIdx.x * 256 + threadIdx.x;        // quad index
    int row = i / (D_INNER / 4);
    int dq  = i - row * (D_INNER / 4);
    float4 yv = ((const float4*)y)[i];
    const float4 gv = *(const float4*)&xpc[(size_t)row * NCOMB + D_INNER + dq * 4];
    float ya[4] = {yv.x, yv.y, yv.z, yv.w};
    float ga[4] = {gv.x, gv.y, gv.z, gv.w};
    float hf[4], lf[4];
#pragma unroll
    for (int j = 0; j < 4; j++) {
        float v = ya[j] * (1.f / (1.f + expf(-ga[j])));
        __nv_bfloat16 hb = __float2bfloat16(v);
        hf[j] = __bfloat162float(hb);
        lf[j] = v - hf[j];
    }
    ((uint2*)yhi)[i] = make_uint2(pack_bf2(hf[0], hf[1]), pack_bf2(hf[2], hf[3]));
    ((uint2*)ylo)[i] = make_uint2(pack_bf2(lf[0], lf[1]), pack_bf2(lf[2], lf[3]));
}

// -------- layernorm: out = post? + LN(in + res?) * g + b (+ bf16/fp16 emit) --------
__device__ __forceinline__ float block_reduce(float v, float* red) {
    for (int o = 16; o > 0; o >>= 1) v += __shfl_down_sync(0xffffffffu, v, o);
    if ((threadIdx.x & 31) == 0) red[threadIdx.x >> 5] = v;
    __syncthreads();
    float t = 0.f;
#pragma unroll
    for (int w = 0; w < 8; w++) t += red[w];
    return t;
}

__global__ __launch_bounds__(256)
void ln_kernel(const float* __restrict__ in, const float* __restrict__ res,
               const float* __restrict__ post,
               const float* __restrict__ g, const float* __restrict__ b,
               float* __restrict__ out,
               __nv_bfloat16* __restrict__ ohi, __nv_bfloat16* __restrict__ olo,
               __half* __restrict__ of16) {
    __shared__ float red[8];
    const int row = blockIdx.x;
    const int t   = threadIdx.x;
    float v[3], pv[3];
    float s = 0.f;
#pragma unroll
    for (int i = 0; i < 3; i++) {
        int c = t + i * 256;
        float x = in[(size_t)row * D_MODEL + c];
        if (res) x += res[(size_t)row * D_MODEL + c];
        pv[i] = post ? post[(size_t)row * D_MODEL + c] : 0.f;
        v[i] = x;
        s += x;
    }
    float tot = block_reduce(s, red);
    float mu = tot * (1.f / D_MODEL);
    __syncthreads();
    float q = 0.f;
#pragma unroll
    for (int i = 0; i < 3; i++) {
        float dd = v[i] - mu;
        q += dd * dd;
    }
    float qtot = block_reduce(q, red);
    float rs = rsqrtf(qtot * (1.f / D_MODEL) + LN_EPS);
#pragma unroll
    for (int i = 0; i < 3; i++) {
        int c = t + i * 256;
        float o = pv[i] + (v[i] - mu) * rs * g[c] + b[c];
        size_t idx = (size_t)row * D_MODEL + c;
        out[idx] = o;
        if (ohi) {
            __nv_bfloat16 h = __float2bfloat16(o);
            ohi[idx] = h;
            olo[idx] = __float2bfloat16(o - __bfloat162float(h));
        }
        if (of16) of16[idx] = __float2half(o);
    }
}

// ---------------- launch ----------------
extern "C" void kernel_launch(void* const* d_in, const int* in_sizes, int n_in,
                              void* d_out, int out_size) {
    const int*   input_ids = (const int*)  d_in[0];
    const float* emb       = (const float*)d_in[1];
    const float* W_in      = (const float*)d_in[2];   // [2, 3072, 768]
    const float* W_dt      = (const float*)d_in[3];   // [2, 1536, 768]
    const float* b_dt      = (const float*)d_in[4];
    const float* dt_bias   = (const float*)d_in[5];
    const float* W_B       = (const float*)d_in[6];
    const float* W_C       = (const float*)d_in[7];
    const float* Amat      = (const float*)d_in[8];
    const float* Dvec      = (const float*)d_in[9];
    const float* W_out     = (const float*)d_in[10];  // [2, 768, 1536]
    const float* ln_g      = (const float*)d_in[11];
    const float* ln_b      = (const float*)d_in[12];
    const float* fin_g     = (const float*)d_in[13];
    const float* fin_b     = (const float*)d_in[14];
    float* logits = (float*)d_out;                    // [4096, 32000]

    float *x, *xpc, *Bm, *Cm, *y, *o;
    __nv_bfloat16 *xhi, *xlo, *yhi, *ylo;
    __nv_bfloat16 *wchi, *wclo, *wohi, *wolo;
    __half *xf16, *ef16;
    cudaGetSymbolAddress((void**)&x,   g_x);
    cudaGetSymbolAddress((void**)&xpc, g_xpc);
    cudaGetSymbolAddress((void**)&Bm,  g_Bm);
    cudaGetSymbolAddress((void**)&Cm,  g_Cm);
    cudaGetSymbolAddress((void**)&y,   g_y);
    cudaGetSymbolAddress((void**)&o,   g_o);
    cudaGetSymbolAddress((void**)&xhi, g_xhi);
    cudaGetSymbolAddress((void**)&xlo, g_xlo);
    cudaGetSymbolAddress((void**)&yhi, g_yhi);
    cudaGetSymbolAddress((void**)&ylo, g_ylo);
    cudaGetSymbolAddress((void**)&wchi, g_wchi);
    cudaGetSymbolAddress((void**)&wclo, g_wclo);
    cudaGetSymbolAddress((void**)&wohi, g_wohi);
    cudaGetSymbolAddress((void**)&wolo, g_wolo);
    cudaGetSymbolAddress((void**)&xf16, g_xf16);
    cudaGetSymbolAddress((void**)&ef16, g_ef16);

    cudaFuncSetAttribute(gemm_split, cudaFuncAttributeMaxDynamicSharedMemorySize,
                         GEMM_SMEM);
    cudaFuncSetAttribute(gemm_fp16_plain, cudaFuncAttributeMaxDynamicSharedMemorySize,
                         GEMM16_SMEM);

    embed_kernel<<<NTOK, D_MODEL / 4>>>(input_ids, emb, x, xhi, xlo);

    // hoisted splits: combined [W_in | W_dt] per layer, W_out, emb->fp16
    for (int l = 0; l < N_LAYERS; l++) {
        int n4 = 2 * D_INNER * D_MODEL / 4;     // W_in layer slice
        split_kernel<<<(n4 + 255) / 256, 256>>>(
            W_in + (size_t)l * 2 * D_INNER * D_MODEL,
            wchi + (size_t)l * NCOMB * D_MODEL,
            wclo + (size_t)l * NCOMB * D_MODEL, n4);
        n4 = D_INNER * D_MODEL / 4;             // W_dt layer slice
        split_kernel<<<(n4 + 255) / 256, 256>>>(
            W_dt + (size_t)l * D_INNER * D_MODEL,
            wchi + (size_t)l * NCOMB * D_MODEL + (size_t)SPLIT_COL * D_MODEL,
            wclo + (size_t)l * NCOMB * D_MODEL + (size_t)SPLIT_COL * D_MODEL, n4);
    }
    {
        int n4 = N_LAYERS * D_MODEL * D_INNER / 4;
        split_kernel<<<(n4 + 255) / 256, 256>>>(W_out, wohi, wolo, n4);
        n4 = VOCAB * D_MODEL / 4;
        conv_fp16_kernel<<<(n4 + 255) / 256, 256>>>(emb, ef16, n4);
    }

    for (int l = 0; l < N_LAYERS; l++) {
        const size_t oWc = (size_t)l * NCOMB * D_MODEL;
        const size_t oWo = (size_t)l * D_MODEL * D_INNER;
        const float* bd = b_dt    + (size_t)l * D_INNER;
        const float* db = dt_bias + (size_t)l * D_INNER;
        const float* Wb = W_B   + (size_t)l * D_STATE * D_MODEL;
        const float* Wc = W_C   + (size_t)l * D_STATE * D_MODEL;
        const float* Al = Amat  + (size_t)l * D_INNER * D_STATE;
        const float* Dl = Dvec  + (size_t)l * D_INNER;
        const float* lg = ln_g  + (size_t)l * D_MODEL;
        const float* lb = ln_b  + (size_t)l * D_MODEL;

        // [xp | gate | dt] = x @ [W_in ; W_dt]^T : [4096, 4608]
        // (softplus fused for columns >= 3072)
        gemm_split<<<dim3(NTOK / 128, NCOMB / 128), 256, GEMM_SMEM>>>(
            xhi, xlo, wchi + oWc, wclo + oWc, xpc, NTOK, NCOMB, D_MODEL,
            1, bd, db);
        bc_gemm<<<NTOK / 8, 256>>>(x, Wb, Wc, Bm, Cm);
        ssm_scan<<<dim3(D_INNER / 64, BATCH), 128>>>(xpc, Bm, Cm, Al, Dl, y);
        gate_mul<<<NTOK * D_INNER / 4 / 256, 256>>>(y, xpc, yhi, ylo);
        // o = (y*gate) @ W_out^T : [4096, 768], K=1536
        gemm_split<<<dim3(NTOK / 128, D_MODEL / 128), 256, GEMM_SMEM>>>(
            yhi, ylo, wohi + oWo, wolo + oWo, o, NTOK, D_MODEL, D_INNER,
            0, nullptr, nullptr);
        // x <- x + LN(o + x)  (emit bf16 split x for next layer's GEMMs)
        ln_kernel<<<NTOK, 256>>>(o, x, x, lg, lb, x, xhi, xlo, nullptr);
    }

    // final LN (emit fp16 x for logits GEMM)
    ln_kernel<<<NTOK, 256>>>(x, nullptr, nullptr, fin_g, fin_b, x,
                             nullptr, nullptr, xf16);
    // logits = x @ emb^T : [4096, 32000]  (plain fp16, 2-stage pipeline)
    gemm_fp16_plain<<<dim3(NTOK / 128, VOCAB / 128), 256, GEMM16_SMEM>>>(
        xf16, ef16, logits, NTOK, VOCAB, D_MODEL);
}

// round 15
// speedup vs baseline: 1.4062x; 1.0677x over previous
#include <cuda_runtime.h>
#include <cuda_bf16.h>
#include <cuda_fp16.h>
#include <math.h>
#include <stdint.h>

// ---------------- problem constants ----------------
#define D_MODEL  768
#define N_LAYERS 2
#define D_STATE  16
#define VOCAB    32000
#define D_INNER  1536            // 2*D_MODEL
#define BATCH    2
#define SEQ      2048
#define NTOK     (BATCH*SEQ)     // 4096
#define LN_EPS   1e-5f
#define NCOMB    4608            // [x_ssm | gate | dt] combined width
#define SPLIT_COL 3072           // softplus region starts here

// ---------------- scratch ----------------
__device__ static float g_x  [NTOK * D_MODEL];
__device__ static float g_xpc[NTOK * NCOMB];     // combined xp|gate|dt
__device__ static float g_Bm [NTOK * D_STATE];
__device__ static float g_Cm [NTOK * D_STATE];
__device__ static float g_y  [NTOK * D_INNER];
__device__ static float g_o  [NTOK * D_MODEL];
// fp16 operands
__device__ static __half g_xf16[NTOK * D_MODEL];
__device__ static __half g_yf16[NTOK * D_INNER];
__device__ static __half g_wchi[N_LAYERS * NCOMB * D_MODEL];   // W_in|W_dt hi
__device__ static __half g_wclo[N_LAYERS * NCOMB * D_MODEL];   // lo
__device__ static __half g_wohi[N_LAYERS * D_MODEL * D_INNER];
__device__ static __half g_wolo[N_LAYERS * D_MODEL * D_INNER];
__device__ static __half g_ef16[VOCAB * D_MODEL];

// ======================= helpers =======================
#define SW128X(o) ((o) ^ (((o) >> 3) & 0x70))

__device__ __forceinline__ uint32_t s2u(const void* p) {
    uint32_t a;
    asm("{ .reg .u64 t; cvta.to.shared.u64 t, %1; cvt.u32.u64 %0, t; }"
        : "=r"(a) : "l"(p));
    return a;
}

__device__ __forceinline__ void ldsm4(uint32_t* r, uint32_t addr) {
    asm volatile("ldmatrix.sync.aligned.m8n8.x4.shared.b16 {%0,%1,%2,%3}, [%4];"
                 : "=r"(r[0]), "=r"(r[1]), "=r"(r[2]), "=r"(r[3]) : "r"(addr));
}

__device__ __forceinline__ void mma_fp16(float* c, const uint32_t* a,
                                         uint32_t b0, uint32_t b1) {
    asm volatile(
        "mma.sync.aligned.m16n8k16.row.col.f32.f16.f16.f32 "
        "{%0,%1,%2,%3}, {%4,%5,%6,%7}, {%8,%9}, {%0,%1,%2,%3};"
        : "+f"(c[0]), "+f"(c[1]), "+f"(c[2]), "+f"(c[3])
        : "r"(a[0]), "r"(a[1]), "r"(a[2]), "r"(a[3]), "r"(b0), "r"(b1));
}

__device__ __forceinline__ void cp16(uint32_t saddr, const void* gaddr) {
    asm volatile("cp.async.ca.shared.global [%0], [%1], 16;"
                 :: "r"(saddr), "l"(gaddr) : "memory");
}

__device__ __forceinline__ uint32_t pack_hf2(float a, float b) {
    __half2 t = __floats2half2_rn(a, b);
    return *(uint32_t*)&t;
}

// ===== one-sided fp16 2-term GEMM: C = A @ (Bhi+Blo)^T, 2-stage pipeline =====
// A single fp16 (activations), B split fp16 hi/lo (weights). Tile 128x128,
// K-chunk 64, stage = 48KB, 2 stages = 96KB -> 2 CTAs/SM (proven recipe).
// mode 1: softplus/clip for columns >= SPLIT_COL (biases indexed c-SPLIT_COL).
#define T2_A   0
#define T2_BH  16384
#define T2_BL  32768
#define T2_STG 49152
#define GEMM2T_SMEM (2 * T2_STG)    // 98304

__global__ void __launch_bounds__(256, 2)
gemm_f16_2t(const __half* __restrict__ A,
            const __half* __restrict__ Bhi, const __half* __restrict__ Blo,
            float* __restrict__ C, int M, int N, int K,
            int mode, const float* __restrict__ eb1, const float* __restrict__ eb2) {
    extern __shared__ char smc[];
    const uint32_t sb = s2u(smc);
    const int tid = threadIdx.x;
    const int wid = tid >> 5, lid = tid & 31;
    const int wm = wid & 1, wn = wid >> 1;          // warp grid 2(M) x 4(N)
    const int bm = blockIdx.x * 128, bn = blockIdx.y * 128;

    const int rin = lid & 7;
    const uint32_t xr = (uint32_t)rin << 4;
    const int amat = lid >> 3;
    const uint32_t aKq = (uint32_t)(amat >> 1) * 16;
    uint32_t aRow[4];
#pragma unroll
    for (int mt = 0; mt < 4; mt++)
        aRow[mt] = (uint32_t)(wm * 64 + mt * 16 + (amat & 1) * 8 + rin) * 128;
    const int bpair = lid >> 4, bsub = (lid >> 3) & 1;
    const uint32_t bKq = (uint32_t)bsub * 16;
    uint32_t bRow[2];
#pragma unroll
    for (int p = 0; p < 2; p++)
        bRow[p] = (uint32_t)(wn * 32 + p * 16 + bpair * 8 + rin) * 128;

    const int grow = tid >> 1;
    const int gch0 = (tid & 1) * 4;
    uint32_t sOff[4];
#pragma unroll
    for (int j = 0; j < 4; j++)
        sOff[j] = SW128X((uint32_t)grow * 128 + (uint32_t)(gch0 + j) * 16);

    const __half* gA  = A   + (size_t)(bm + grow) * K + gch0 * 8;
    const __half* gBh = Bhi + (size_t)(bn + grow) * K + gch0 * 8;
    const __half* gBl = Blo + (size_t)(bn + grow) * K + gch0 * 8;

    float acc[4][4][4];
#pragma unroll
    for (int mt = 0; mt < 4; mt++)
#pragma unroll
        for (int nt = 0; nt < 4; nt++)
#pragma unroll
            for (int i = 0; i < 4; i++) acc[mt][nt][i] = 0.f;

    const int NC = K / 64;

    // prologue: chunk 0 -> stage 0
    {
#pragma unroll
        for (int j = 0; j < 4; j++) {
            cp16(sb + T2_A  + sOff[j], gA  + j * 8);
            cp16(sb + T2_BH + sOff[j], gBh + j * 8);
            cp16(sb + T2_BL + sOff[j], gBl + j * 8);
        }
        asm volatile("cp.async.commit_group;" ::: "memory");
    }

    for (int c = 0; c < NC; c++) {
        if (c + 1 < NC) {
            const uint32_t st1 = sb + (uint32_t)((c + 1) & 1) * T2_STG;
            const int k1 = (c + 1) * 64;
#pragma unroll
            for (int j = 0; j < 4; j++) {
                cp16(st1 + T2_A  + sOff[j], gA  + k1 + j * 8);
                cp16(st1 + T2_BH + sOff[j], gBh + k1 + j * 8);
                cp16(st1 + T2_BL + sOff[j], gBl + k1 + j * 8);
            }
            asm volatile("cp.async.commit_group;" ::: "memory");
            asm volatile("cp.async.wait_group 1;" ::: "memory");
        } else {
            asm volatile("cp.async.wait_group 0;" ::: "memory");
        }
        __syncthreads();

        const uint32_t st = sb + (uint32_t)(c & 1) * T2_STG;
#pragma unroll
        for (int ks = 0; ks < 4; ks++) {
            const uint32_t aoff = (((uint32_t)ks * 32 + aKq) ^ xr);
            const uint32_t boff = (((uint32_t)ks * 32 + bKq) ^ xr);
            uint32_t ah[4][4], bb[2][4];
#pragma unroll
            for (int mt = 0; mt < 4; mt++)
                ldsm4(ah[mt], st + T2_A + aRow[mt] + aoff);
            // A x Bhi
#pragma unroll
            for (int p = 0; p < 2; p++)
                ldsm4(bb[p], st + T2_BH + bRow[p] + boff);
#pragma unroll
            for (int mt = 0; mt < 4; mt++)
#pragma unroll
                for (int nt = 0; nt < 4; nt++)
                    mma_fp16(acc[mt][nt], ah[mt],
                             bb[nt >> 1][(nt & 1) * 2], bb[nt >> 1][(nt & 1) * 2 + 1]);
            // A x Blo (reuse ah)
#pragma unroll
            for (int p = 0; p < 2; p++)
                ldsm4(bb[p], st + T2_BL + bRow[p] + boff);
#pragma unroll
            for (int mt = 0; mt < 4; mt++)
#pragma unroll
                for (int nt = 0; nt < 4; nt++)
                    mma_fp16(acc[mt][nt], ah[mt],
                             bb[nt >> 1][(nt & 1) * 2], bb[nt >> 1][(nt & 1) * 2 + 1]);
        }
        __syncthreads();   // stage consumed
    }

    const int gid = lid >> 2, tig = lid & 3;
#pragma unroll
    for (int mt = 0; mt < 4; mt++) {
#pragma unroll
        for (int nt = 0; nt < 4; nt++) {
            int r0 = bm + wm * 64 + mt * 16 + gid;
            int c0 = bn + wn * 32 + nt * 8 + tig * 2;
            float v[4] = {acc[mt][nt][0], acc[mt][nt][1],
                          acc[mt][nt][2], acc[mt][nt][3]};
            if (mode == 1 && c0 >= SPLIT_COL) {
                int cb = c0 - SPLIT_COL;
                float bb0 = eb1[cb] + eb2[cb];
                float bb1 = eb1[cb + 1] + eb2[cb + 1];
#pragma unroll
                for (int i = 0; i < 4; i++) {
                    float t = v[i] + ((i & 1) ? bb1 : bb0);
                    float sp = (t > 20.f) ? t : log1pf(expf(t));
                    v[i] = fminf(fmaxf(sp, 0.f), 1.f);
                }
            }
            *(float2*)&C[(size_t)r0 * N + c0]       = make_float2(v[0], v[1]);
            *(float2*)&C[(size_t)(r0 + 8) * N + c0] = make_float2(v[2], v[3]);
        }
    }
}

// ============ plain fp16 GEMM (logits): 2-stage pipeline, 2 CTAs/SM ==========
#define FP_A   0
#define FP_B   16384
#define FPSTG  32768
#define GEMM16_SMEM (2 * FPSTG)     // 64KB

__global__ void __launch_bounds__(256, 2)
gemm_fp16_plain(const __half* __restrict__ A, const __half* __restrict__ B,
                float* __restrict__ C, int M, int N, int K) {
    extern __shared__ char smc[];
    const uint32_t sb = s2u(smc);
    const int tid = threadIdx.x;
    const int wid = tid >> 5, lid = tid & 31;
    const int wm = wid & 1, wn = wid >> 1;
    const int bm = blockIdx.x * 128, bn = blockIdx.y * 128;

    const int rin = lid & 7;
    const uint32_t xr = (uint32_t)rin << 4;
    const int amat = lid >> 3;
    const uint32_t aKq = (uint32_t)(amat >> 1) * 16;
    uint32_t aRow[4];
#pragma unroll
    for (int mt = 0; mt < 4; mt++)
        aRow[mt] = (uint32_t)(wm * 64 + mt * 16 + (amat & 1) * 8 + rin) * 128;
    const int bpair = lid >> 4, bsub = (lid >> 3) & 1;
    const uint32_t bKq = (uint32_t)bsub * 16;
    uint32_t bRow[2];
#pragma unroll
    for (int p = 0; p < 2; p++)
        bRow[p] = (uint32_t)(wn * 32 + p * 16 + bpair * 8 + rin) * 128;

    const int grow = tid >> 1;
    const int gch0 = (tid & 1) * 4;
    uint32_t sOff[4];
#pragma unroll
    for (int j = 0; j < 4; j++)
        sOff[j] = SW128X((uint32_t)grow * 128 + (uint32_t)(gch0 + j) * 16);

    const __half* gA = A + (size_t)(bm + grow) * K + gch0 * 8;
    const __half* gB = B + (size_t)(bn + grow) * K + gch0 * 8;

    float acc[4][4][4];
#pragma unroll
    for (int mt = 0; mt < 4; mt++)
#pragma unroll
        for (int nt = 0; nt < 4; nt++)
#pragma unroll
            for (int i = 0; i < 4; i++) acc[mt][nt][i] = 0.f;

    const int NC = K / 64;
    {
#pragma unroll
        for (int j = 0; j < 4; j++) {
            cp16(sb + FP_A + sOff[j], gA + j * 8);
            cp16(sb + FP_B + sOff[j], gB + j * 8);
        }
        asm volatile("cp.async.commit_group;" ::: "memory");
    }

    for (int c = 0; c < NC; c++) {
        if (c + 1 < NC) {
            const uint32_t st1 = sb + (uint32_t)((c + 1) & 1) * FPSTG;
            const int k1 = (c + 1) * 64;
#pragma unroll
            for (int j = 0; j < 4; j++) {
                cp16(st1 + FP_A + sOff[j], gA + k1 + j * 8);
                cp16(st1 + FP_B + sOff[j], gB + k1 + j * 8);
            }
            asm volatile("cp.async.commit_group;" ::: "memory");
            asm volatile("cp.async.wait_group 1;" ::: "memory");
        } else {
            asm volatile("cp.async.wait_group 0;" ::: "memory");
        }
        __syncthreads();

        const uint32_t st = sb + (uint32_t)(c & 1) * FPSTG;
#pragma unroll
        for (int ks = 0; ks < 4; ks++) {
            const uint32_t aoff = (((uint32_t)ks * 32 + aKq) ^ xr);
            const uint32_t boff = (((uint32_t)ks * 32 + bKq) ^ xr);
            uint32_t ah[4][4], bb[2][4];
#pragma unroll
            for (int mt = 0; mt < 4; mt++)
                ldsm4(ah[mt], st + FP_A + aRow[mt] + aoff);
#pragma unroll
            for (int p = 0; p < 2; p++)
                ldsm4(bb[p], st + FP_B + bRow[p] + boff);
#pragma unroll
            for (int mt = 0; mt < 4; mt++)
#pragma unroll
                for (int nt = 0; nt < 4; nt++)
                    mma_fp16(acc[mt][nt], ah[mt],
                             bb[nt >> 1][(nt & 1) * 2], bb[nt >> 1][(nt & 1) * 2 + 1]);
        }
        __syncthreads();
    }

    const int gid = lid >> 2, tig = lid & 3;
#pragma unroll
    for (int mt = 0; mt < 4; mt++) {
#pragma unroll
        for (int nt = 0; nt < 4; nt++) {
            int r0 = bm + wm * 64 + mt * 16 + gid;
            int c0 = bn + wn * 32 + nt * 8 + tig * 2;
            *(float2*)&C[(size_t)r0 * N + c0] =
                make_float2(acc[mt][nt][0], acc[mt][nt][1]);
            *(float2*)&C[(size_t)(r0 + 8) * N + c0] =
                make_float2(acc[mt][nt][2], acc[mt][nt][3]);
        }
    }
}

// ------------- vectorized fp32 -> (hi, lo) fp16 split ----------------
__global__ void split_fp16_kernel(const float* __restrict__ src,
                                  __half* __restrict__ hi,
                                  __half* __restrict__ lo, int n4) {
    int i = blockIdx.x * 256 + threadIdx.x;
    if (i < n4) {
        float4 v = ((const float4*)src)[i];
        float a[4] = {v.x, v.y, v.z, v.w};
        float hf[4], lf[4];
#pragma unroll
        for (int j = 0; j < 4; j++) {
            __half h = __float2half(a[j]);
            hf[j] = __half2float(h);
            lf[j] = a[j] - hf[j];
        }
        ((uint2*)hi)[i] = make_uint2(pack_hf2(hf[0], hf[1]), pack_hf2(hf[2], hf[3]));
        ((uint2*)lo)[i] = make_uint2(pack_hf2(lf[0], lf[1]), pack_hf2(lf[2], lf[3]));
    }
}

// ------------- vectorized fp32 -> fp16 convert ----------------
__global__ void conv_fp16_kernel(const float* __restrict__ src,
                                 __half* __restrict__ dst, int n4) {
    int i = blockIdx.x * 256 + threadIdx.x;
    if (i < n4) {
        float4 v = ((const float4*)src)[i];
        ((uint2*)dst)[i] = make_uint2(pack_hf2(v.x, v.y), pack_hf2(v.z, v.w));
    }
}

// ---------------- embedding gather (+ fp16 emit) ----------------
__global__ void embed_kernel(const int* __restrict__ ids,
                             const float* __restrict__ emb,
                             float* __restrict__ x,
                             __half* __restrict__ xf16) {
    int row = blockIdx.x;
    int id  = ids[row];
    float4 v = ((const float4*)(emb + (size_t)id * D_MODEL))[threadIdx.x];
    ((float4*)(x + (size_t)row * D_MODEL))[threadIdx.x] = v;
    ((uint2*)(xf16 + (size_t)row * D_MODEL))[threadIdx.x] =
        make_uint2(pack_hf2(v.x, v.y), pack_hf2(v.z, v.w));
}

// ---------------- skinny GEMM for B/C projections (N=16 each) ----------------
__global__ __launch_bounds__(256)
void bc_gemm(const float* __restrict__ x, const float* __restrict__ Wb,
             const float* __restrict__ Wc, float* __restrict__ Bm,
             float* __restrict__ Cm) {
    __shared__ float xs[8][D_MODEL];
    int row0 = blockIdx.x * 8;
    const float4* xg = (const float4*)(x + (size_t)row0 * D_MODEL);
    float4* xsv = (float4*)xs;
    for (int i = threadIdx.x; i < 8 * D_MODEL / 4; i += 256) xsv[i] = xg[i];
    __syncthreads();

    int r = threadIdx.x >> 5;
    int c = threadIdx.x & 31;
    const float* W = (c < 16) ? (Wb + (size_t)c * D_MODEL)
                              : (Wc + (size_t)(c - 16) * D_MODEL);
    const float4* Wv = (const float4*)W;
    const float4* xr = (const float4*)xs[r];
    float s = 0.f;
#pragma unroll 4
    for (int k = 0; k < D_MODEL / 4; k++) {
        float4 w = Wv[k], v = xr[k];
        s += w.x * v.x + w.y * v.y + w.z * v.z + w.w * v.w;
    }
    if (c < 16) Bm[(size_t)(row0 + r) * D_STATE + c]        = s;
    else        Cm[(size_t)(row0 + r) * D_STATE + (c - 16)] = s;
}

// ======== SSM scan: TCH=32 double-buffered (proven); reads combined buffer ========
#define TCH 32
__global__ __launch_bounds__(128)
void ssm_scan(const float* __restrict__ xpc,
              const float* __restrict__ Bm, const float* __restrict__ Cm,
              const float* __restrict__ Amat, const float* __restrict__ Dvec,
              float* __restrict__ yout) {
    __shared__ float  xp_s[2][TCH][64];
    __shared__ float  dt_s[2][TCH][64];
    __shared__ float4 B_s [2][TCH][4];
    __shared__ float4 C_s [2][TCH][4];

    const int tid = threadIdx.x;
    const int wid = tid >> 5, lid = tid & 31;
    const int ch   = wid * 16 + (lid & 15);      // 0..63 local channel
    const int half = lid >> 4;                   // states [0,8) or [8,16)
    const int d0 = blockIdx.x * 64;
    const int d  = d0 + ch;
    const int b  = blockIdx.y;

    float Ar[8], h[8];
#pragma unroll
    for (int j = 0; j < 8; j++) {
        Ar[j] = Amat[(size_t)d * D_STATE + half * 8 + j];
        h[j]  = 0.f;
    }
    const float Dd = Dvec[d];

    const int tt0 = tid >> 4;            // 0..7
    const int seg = (tid & 15) * 4;      // float offset within 64-ch row

    auto issue_chunk = [&](int buf, int tc) {
#pragma unroll
        for (int r = 0; r < 4; r++) {
            int tt = tt0 + r * 8;
            size_t row = (size_t)b * SEQ + tc + tt;
            cp16(s2u(&xp_s[buf][tt][seg]), xpc + row * NCOMB + d0 + seg);
            cp16(s2u(&dt_s[buf][tt][seg]), xpc + row * NCOMB + SPLIT_COL + d0 + seg);
        }
        size_t bcbase = ((size_t)b * SEQ + tc) * D_STATE;
        cp16(s2u((float*)B_s[buf] + tid * 4), Bm + bcbase + tid * 4);
        cp16(s2u((float*)C_s[buf] + tid * 4), Cm + bcbase + tid * 4);
        asm volatile("cp.async.commit_group;" ::: "memory");
    };

    issue_chunk(0, 0);
    const int NCH = SEQ / TCH;
    for (int c = 0; c < NCH; c++) {
        const int buf = c & 1;
        if (c + 1 < NCH) {
            issue_chunk(buf ^ 1, (c + 1) * TCH);
            asm volatile("cp.async.wait_group 1;" ::: "memory");
        } else {
            asm volatile("cp.async.wait_group 0;" ::: "memory");
        }
        __syncthreads();

        const int tcg = c * TCH;
#pragma unroll 4
        for (int tt = 0; tt < TCH; tt++) {
            float u  = xp_s[buf][tt][ch];
            float dv = dt_s[buf][tt][ch];
            float4 Bv0 = B_s[buf][tt][half * 2];
            float4 Bv1 = B_s[buf][tt][half * 2 + 1];
            float4 Cv0 = C_s[buf][tt][half * 2];
            float4 Cv1 = C_s[buf][tt][half * 2 + 1];
            float bs[8] = {Bv0.x, Bv0.y, Bv0.z, Bv0.w, Bv1.x, Bv1.y, Bv1.z, Bv1.w};
            float cs[8] = {Cv0.x, Cv0.y, Cv0.z, Cv0.w, Cv1.x, Cv1.y, Cv1.z, Cv1.w};
            float u01 = 0.1f * u;
            float adt = 0.1f * dv;
            float p0 = 0.f, p1 = 0.f;
#pragma unroll
            for (int j = 0; j < 8; j++) {
                float hv = h[j];
                hv = fmaf(hv * Ar[j], adt, fmaf(bs[j], u01, hv));
                h[j] = hv;
                float p = hv * cs[j];
                if (j & 1) p1 += p; else p0 += p;
            }
            float part = p0 + p1;
            float tot = part + __shfl_xor_sync(0xffffffffu, part, 16);
            if (!half)
                yout[((size_t)b * SEQ + tcg + tt) * D_INNER + d] = Dd * u + tot;
        }
        __syncthreads();
    }
}

// ---------------- gate multiply -> fp16 y (4 elems/thread) ----------------
__global__ void gate_mul(const float* __restrict__ y, const float* __restrict__ xpc,
                         __half* __restrict__ yf16) {
    int i = blockIdx.x * 256 + threadIdx.x;        // quad index
    int row = i / (D_INNER / 4);
    int dq  = i - row * (D_INNER / 4);
    float4 yv = ((const float4*)y)[i];
    const float4 gv = *(const float4*)&xpc[(size_t)row * NCOMB + D_INNER + dq * 4];
    float va = yv.x * (1.f / (1.f + expf(-gv.x)));
    float vb = yv.y * (1.f / (1.f + expf(-gv.y)));
    float vc = yv.z * (1.f / (1.f + expf(-gv.z)));
    float vd = yv.w * (1.f / (1.f + expf(-gv.w)));
    ((uint2*)yf16)[i] = make_uint2(pack_hf2(va, vb), pack_hf2(vc, vd));
}

// -------- layernorm: out = post? + LN(in + res?) * g + b (+ fp16 emit) --------
__device__ __forceinline__ float block_reduce(float v, float* red) {
    for (int o = 16; o > 0; o >>= 1) v += __shfl_down_sync(0xffffffffu, v, o);
    if ((threadIdx.x & 31) == 0) red[threadIdx.x >> 5] = v;
    __syncthreads();
    float t = 0.f;
#pragma unroll
    for (int w = 0; w < 8; w++) t += red[w];
    return t;
}

__global__ __launch_bounds__(256)
void ln_kernel(const float* __restrict__ in, const float* __restrict__ res,
               const float* __restrict__ post,
               const float* __restrict__ g, const float* __restrict__ b,
               float* __restrict__ out, __half* __restrict__ of16) {
    __shared__ float red[8];
    const int row = blockIdx.x;
    const int t   = threadIdx.x;
    float v[3], pv[3];
    float s = 0.f;
#pragma unroll
    for (int i = 0; i < 3; i++) {
        int c = t + i * 256;
        float x = in[(size_t)row * D_MODEL + c];
        if (res) x += res[(size_t)row * D_MODEL + c];
        pv[i] = post ? post[(size_t)row * D_MODEL + c] : 0.f;
        v[i] = x;
        s += x;
    }
    float tot = block_reduce(s, red);
    float mu = tot * (1.f / D_MODEL);
    __syncthreads();
    float q = 0.f;
#pragma unroll
    for (int i = 0; i < 3; i++) {
        float dd = v[i] - mu;
        q += dd * dd;
    }
    float qtot = block_reduce(q, red);
    float rs = rsqrtf(qtot * (1.f / D_MODEL) + LN_EPS);
#pragma unroll
    for (int i = 0; i < 3; i++) {
        int c = t + i * 256;
        float o = pv[i] + (v[i] - mu) * rs * g[c] + b[c];
        size_t idx = (size_t)row * D_MODEL + c;
        out[idx] = o;
        of16[idx] = __float2half(o);
    }
}

// ---------------- launch ----------------
extern "C" void kernel_launch(void* const* d_in, const int* in_sizes, int n_in,
                              void* d_out, int out_size) {
    const int*   input_ids = (const int*)  d_in[0];
    const float* emb       = (const float*)d_in[1];
    const float* W_in      = (const float*)d_in[2];   // [2, 3072, 768]
    const float* W_dt      = (const float*)d_in[3];   // [2, 1536, 768]
    const float* b_dt      = (const float*)d_in[4];
    const float* dt_bias   = (const float*)d_in[5];
    const float* W_B       = (const float*)d_in[6];
    const float* W_C       = (const float*)d_in[7];
    const float* Amat      = (const float*)d_in[8];
    const float* Dvec      = (const float*)d_in[9];
    const float* W_out     = (const float*)d_in[10];  // [2, 768, 1536]
    const float* ln_g      = (const float*)d_in[11];
    const float* ln_b      = (const float*)d_in[12];
    const float* fin_g     = (const float*)d_in[13];
    const float* fin_b     = (const float*)d_in[14];
    float* logits = (float*)d_out;                    // [4096, 32000]

    float *x, *xpc, *Bm, *Cm, *y, *o;
    __half *xf16, *yf16, *wchi, *wclo, *wohi, *wolo, *ef16;
    cudaGetSymbolAddress((void**)&x,   g_x);
    cudaGetSymbolAddress((void**)&xpc, g_xpc);
    cudaGetSymbolAddress((void**)&Bm,  g_Bm);
    cudaGetSymbolAddress((void**)&Cm,  g_Cm);
    cudaGetSymbolAddress((void**)&y,   g_y);
    cudaGetSymbolAddress((void**)&o,   g_o);
    cudaGetSymbolAddress((void**)&xf16, g_xf16);
    cudaGetSymbolAddress((void**)&yf16, g_yf16);
    cudaGetSymbolAddress((void**)&wchi, g_wchi);
    cudaGetSymbolAddress((void**)&wclo, g_wclo);
    cudaGetSymbolAddress((void**)&wohi, g_wohi);
    cudaGetSymbolAddress((void**)&wolo, g_wolo);
    cudaGetSymbolAddress((void**)&ef16, g_ef16);

    cudaFuncSetAttribute(gemm_f16_2t, cudaFuncAttributeMaxDynamicSharedMemorySize,
                         GEMM2T_SMEM);
    cudaFuncSetAttribute(gemm_fp16_plain, cudaFuncAttributeMaxDynamicSharedMemorySize,
                         GEMM16_SMEM);

    embed_kernel<<<NTOK, D_MODEL / 4>>>(input_ids, emb, x, xf16);

    // hoisted splits: combined [W_in | W_dt] per layer, W_out, emb->fp16
    for (int l = 0; l < N_LAYERS; l++) {
        int n4 = 2 * D_INNER * D_MODEL / 4;
        split_fp16_kernel<<<(n4 + 255) / 256, 256>>>(
            W_in + (size_t)l * 2 * D_INNER * D_MODEL,
            wchi + (size_t)l * NCOMB * D_MODEL,
            wclo + (size_t)l * NCOMB * D_MODEL, n4);
        n4 = D_INNER * D_MODEL / 4;
        split_fp16_kernel<<<(n4 + 255) / 256, 256>>>(
            W_dt + (size_t)l * D_INNER * D_MODEL,
            wchi + (size_t)l * NCOMB * D_MODEL + (size_t)SPLIT_COL * D_MODEL,
            wclo + (size_t)l * NCOMB * D_MODEL + (size_t)SPLIT_COL * D_MODEL, n4);
    }
    {
        int n4 = N_LAYERS * D_MODEL * D_INNER / 4;
        split_fp16_kernel<<<(n4 + 255) / 256, 256>>>(W_out, wohi, wolo, n4);
        n4 = VOCAB * D_MODEL / 4;
        conv_fp16_kernel<<<(n4 + 255) / 256, 256>>>(emb, ef16, n4);
    }

    for (int l = 0; l < N_LAYERS; l++) {
        const size_t oWc = (size_t)l * NCOMB * D_MODEL;
        const size_t oWo = (size_t)l * D_MODEL * D_INNER;
        const float* bd = b_dt    + (size_t)l * D_INNER;
        const float* db = dt_bias + (size_t)l * D_INNER;
        const float* Wb = W_B   + (size_t)l * D_STATE * D_MODEL;
        const float* Wc = W_C   + (size_t)l * D_STATE * D_MODEL;
        const float* Al = Amat  + (size_t)l * D_INNER * D_STATE;
        const float* Dl = Dvec  + (size_t)l * D_INNER;
        const float* lg = ln_g  + (size_t)l * D_MODEL;
        const float* lb = ln_b  + (size_t)l * D_MODEL;

        // [xp | gate | dt] = x @ [W_in ; W_dt]^T : [4096, 4608], softplus fused
        gemm_f16_2t<<<dim3(NTOK / 128, NCOMB / 128), 256, GEMM2T_SMEM>>>(
            xf16, wchi + oWc, wclo + oWc, xpc, NTOK, NCOMB, D_MODEL,
            1, bd, db);
        bc_gemm<<<NTOK / 8, 256>>>(x, Wb, Wc, Bm, Cm);
        ssm_scan<<<dim3(D_INNER / 64, BATCH), 128>>>(xpc, Bm, Cm, Al, Dl, y);
        gate_mul<<<NTOK * D_INNER / 4 / 256, 256>>>(y, xpc, yf16);
        // o = (y*gate) @ W_out^T : [4096, 768], K=1536
        gemm_f16_2t<<<dim3(NTOK / 128, D_MODEL / 128), 256, GEMM2T_SMEM>>>(
            yf16, wohi + oWo, wolo + oWo, o, NTOK, D_MODEL, D_INNER,
            0, nullptr, nullptr);
        // x <- x + LN(o + x)  (emit fp16 x for next layer's GEMMs)
        ln_kernel<<<NTOK, 256>>>(o, x, x, lg, lb, x, xf16);
    }

    // final LN (emit fp16 x for logits GEMM)
    ln_kernel<<<NTOK, 256>>>(x, nullptr, nullptr, fin_g, fin_b, x, xf16);
    // logits = x @ emb^T : [4096, 32000]  (plain fp16, 2-stage pipeline)
    gemm_fp16_plain<<<dim3(NTOK / 128, VOCAB / 128), 256, GEMM16_SMEM>>>(
        xf16, ef16, logits, NTOK, VOCAB, D_MODEL);
}

// round 16
// speedup vs baseline: 1.6578x; 1.1789x over previous
#include <cuda_runtime.h>
#include <cuda_bf16.h>
#include <cuda_fp16.h>
#include <math.h>
#include <stdint.h>

// ---------------- problem constants ----------------
#define D_MODEL  768
#define N_LAYERS 2
#define D_STATE  16
#define VOCAB    32000
#define D_INNER  1536            // 2*D_MODEL
#define BATCH    2
#define SEQ      2048
#define NTOK     (BATCH*SEQ)     // 4096
#define LN_EPS   1e-5f
#define NCOMB    4608            // [x_ssm | gate | dt] combined width
#define SPLIT_COL 3072           // softplus region starts here

// ---------------- scratch ----------------
__device__ static float g_x  [NTOK * D_MODEL];
__device__ static float g_xpc[NTOK * NCOMB];     // combined xp|gate|dt
__device__ static float g_Bm [NTOK * D_STATE];
__device__ static float g_Cm [NTOK * D_STATE];
__device__ static float g_y  [NTOK * D_INNER];
__device__ static float g_o  [NTOK * D_MODEL];
// fp16 operands (ALL GEMMs now plain fp16)
__device__ static __half g_xf16[NTOK * D_MODEL];
__device__ static __half g_yf16[NTOK * D_INNER];
__device__ static __half g_wcf16[N_LAYERS * NCOMB * D_MODEL];   // [W_in|W_dt]
__device__ static __half g_wof16[N_LAYERS * D_MODEL * D_INNER];
__device__ static __half g_ef16 [VOCAB * D_MODEL];

// ======================= helpers =======================
#define SW128X(o) ((o) ^ (((o) >> 3) & 0x70))

__device__ __forceinline__ uint32_t s2u(const void* p) {
    uint32_t a;
    asm("{ .reg .u64 t; cvta.to.shared.u64 t, %1; cvt.u32.u64 %0, t; }"
        : "=r"(a) : "l"(p));
    return a;
}

__device__ __forceinline__ void ldsm4(uint32_t* r, uint32_t addr) {
    asm volatile("ldmatrix.sync.aligned.m8n8.x4.shared.b16 {%0,%1,%2,%3}, [%4];"
                 : "=r"(r[0]), "=r"(r[1]), "=r"(r[2]), "=r"(r[3]) : "r"(addr));
}

__device__ __forceinline__ void mma_fp16(float* c, const uint32_t* a,
                                         uint32_t b0, uint32_t b1) {
    asm volatile(
        "mma.sync.aligned.m16n8k16.row.col.f32.f16.f16.f32 "
        "{%0,%1,%2,%3}, {%4,%5,%6,%7}, {%8,%9}, {%0,%1,%2,%3};"
        : "+f"(c[0]), "+f"(c[1]), "+f"(c[2]), "+f"(c[3])
        : "r"(a[0]), "r"(a[1]), "r"(a[2]), "r"(a[3]), "r"(b0), "r"(b1));
}

__device__ __forceinline__ void cp16(uint32_t saddr, const void* gaddr) {
    asm volatile("cp.async.ca.shared.global [%0], [%1], 16;"
                 :: "r"(saddr), "l"(gaddr) : "memory");
}

__device__ __forceinline__ uint32_t pack_hf2(float a, float b) {
    __half2 t = __floats2half2_rn(a, b);
    return *(uint32_t*)&t;
}

// ========= plain fp16 GEMM: C = A @ B^T, 2-stage pipeline, 2 CTAs/SM =========
// The single GEMM kernel for ALL matmuls. Tile 128x128, K-chunk 64,
// stage = 32KB, 2 stages = 64KB (proven 2-CTA/SM recipe).
// mode 1: softplus/clip for columns >= SPLIT_COL (biases at c-SPLIT_COL).
#define FP_A   0
#define FP_B   16384
#define FPSTG  32768
#define GEMM16_SMEM (2 * FPSTG)     // 64KB

__global__ void __launch_bounds__(256, 2)
gemm_fp16(const __half* __restrict__ A, const __half* __restrict__ B,
          float* __restrict__ C, int M, int N, int K,
          int mode, const float* __restrict__ eb1, const float* __restrict__ eb2) {
    extern __shared__ char smc[];
    const uint32_t sb = s2u(smc);
    const int tid = threadIdx.x;
    const int wid = tid >> 5, lid = tid & 31;
    const int wm = wid & 1, wn = wid >> 1;          // warp grid 2(M) x 4(N)
    const int bm = blockIdx.x * 128, bn = blockIdx.y * 128;

    const int rin = lid & 7;
    const uint32_t xr = (uint32_t)rin << 4;
    const int amat = lid >> 3;
    const uint32_t aKq = (uint32_t)(amat >> 1) * 16;
    uint32_t aRow[4];
#pragma unroll
    for (int mt = 0; mt < 4; mt++)
        aRow[mt] = (uint32_t)(wm * 64 + mt * 16 + (amat & 1) * 8 + rin) * 128;
    const int bpair = lid >> 4, bsub = (lid >> 3) & 1;
    const uint32_t bKq = (uint32_t)bsub * 16;
    uint32_t bRow[2];
#pragma unroll
    for (int p = 0; p < 2; p++)
        bRow[p] = (uint32_t)(wn * 32 + p * 16 + bpair * 8 + rin) * 128;

    const int grow = tid >> 1;
    const int gch0 = (tid & 1) * 4;
    uint32_t sOff[4];
#pragma unroll
    for (int j = 0; j < 4; j++)
        sOff[j] = SW128X((uint32_t)grow * 128 + (uint32_t)(gch0 + j) * 16);

    const __half* gA = A + (size_t)(bm + grow) * K + gch0 * 8;
    const __half* gB = B + (size_t)(bn + grow) * K + gch0 * 8;

    float acc[4][4][4];
#pragma unroll
    for (int mt = 0; mt < 4; mt++)
#pragma unroll
        for (int nt = 0; nt < 4; nt++)
#pragma unroll
            for (int i = 0; i < 4; i++) acc[mt][nt][i] = 0.f;

    const int NC = K / 64;

    // prologue: chunk 0 -> stage 0
    {
#pragma unroll
        for (int j = 0; j < 4; j++) {
            cp16(sb + FP_A + sOff[j], gA + j * 8);
            cp16(sb + FP_B + sOff[j], gB + j * 8);
        }
        asm volatile("cp.async.commit_group;" ::: "memory");
    }

    for (int c = 0; c < NC; c++) {
        if (c + 1 < NC) {
            const uint32_t st1 = sb + (uint32_t)((c + 1) & 1) * FPSTG;
            const int k1 = (c + 1) * 64;
#pragma unroll
            for (int j = 0; j < 4; j++) {
                cp16(st1 + FP_A + sOff[j], gA + k1 + j * 8);
                cp16(st1 + FP_B + sOff[j], gB + k1 + j * 8);
            }
            asm volatile("cp.async.commit_group;" ::: "memory");
            asm volatile("cp.async.wait_group 1;" ::: "memory");
        } else {
            asm volatile("cp.async.wait_group 0;" ::: "memory");
        }
        __syncthreads();

        const uint32_t st = sb + (uint32_t)(c & 1) * FPSTG;
#pragma unroll
        for (int ks = 0; ks < 4; ks++) {
            const uint32_t aoff = (((uint32_t)ks * 32 + aKq) ^ xr);
            const uint32_t boff = (((uint32_t)ks * 32 + bKq) ^ xr);
            uint32_t ah[4][4], bb[2][4];
#pragma unroll
            for (int mt = 0; mt < 4; mt++)
                ldsm4(ah[mt], st + FP_A + aRow[mt] + aoff);
#pragma unroll
            for (int p = 0; p < 2; p++)
                ldsm4(bb[p], st + FP_B + bRow[p] + boff);
#pragma unroll
            for (int mt = 0; mt < 4; mt++)
#pragma unroll
                for (int nt = 0; nt < 4; nt++)
                    mma_fp16(acc[mt][nt], ah[mt],
                             bb[nt >> 1][(nt & 1) * 2], bb[nt >> 1][(nt & 1) * 2 + 1]);
        }
        __syncthreads();   // stage consumed
    }

    const int gid = lid >> 2, tig = lid & 3;
#pragma unroll
    for (int mt = 0; mt < 4; mt++) {
#pragma unroll
        for (int nt = 0; nt < 4; nt++) {
            int r0 = bm + wm * 64 + mt * 16 + gid;
            int c0 = bn + wn * 32 + nt * 8 + tig * 2;
            float v[4] = {acc[mt][nt][0], acc[mt][nt][1],
                          acc[mt][nt][2], acc[mt][nt][3]};
            if (mode == 1 && c0 >= SPLIT_COL) {
                int cb = c0 - SPLIT_COL;
                float bb0 = eb1[cb] + eb2[cb];
                float bb1 = eb1[cb + 1] + eb2[cb + 1];
#pragma unroll
                for (int i = 0; i < 4; i++) {
                    float t = v[i] + ((i & 1) ? bb1 : bb0);
                    float sp = (t > 20.f) ? t : log1pf(expf(t));
                    v[i] = fminf(fmaxf(sp, 0.f), 1.f);
                }
            }
            *(float2*)&C[(size_t)r0 * N + c0]       = make_float2(v[0], v[1]);
            *(float2*)&C[(size_t)(r0 + 8) * N + c0] = make_float2(v[2], v[3]);
        }
    }
}

// ------------- vectorized fp32 -> fp16 convert ----------------
__global__ void conv_fp16_kernel(const float* __restrict__ src,
                                 __half* __restrict__ dst, int n4) {
    int i = blockIdx.x * 256 + threadIdx.x;
    if (i < n4) {
        float4 v = ((const float4*)src)[i];
        ((uint2*)dst)[i] = make_uint2(pack_hf2(v.x, v.y), pack_hf2(v.z, v.w));
    }
}

// ---------------- embedding gather (+ fp16 emit) ----------------
__global__ void embed_kernel(const int* __restrict__ ids,
                             const float* __restrict__ emb,
                             float* __restrict__ x,
                             __half* __restrict__ xf16) {
    int row = blockIdx.x;
    int id  = ids[row];
    float4 v = ((const float4*)(emb + (size_t)id * D_MODEL))[threadIdx.x];
    ((float4*)(x + (size_t)row * D_MODEL))[threadIdx.x] = v;
    ((uint2*)(xf16 + (size_t)row * D_MODEL))[threadIdx.x] =
        make_uint2(pack_hf2(v.x, v.y), pack_hf2(v.z, v.w));
}

// ---------------- skinny GEMM for B/C projections (N=16 each) ----------------
__global__ __launch_bounds__(256)
void bc_gemm(const float* __restrict__ x, const float* __restrict__ Wb,
             const float* __restrict__ Wc, float* __restrict__ Bm,
             float* __restrict__ Cm) {
    __shared__ float xs[8][D_MODEL];
    int row0 = blockIdx.x * 8;
    const float4* xg = (const float4*)(x + (size_t)row0 * D_MODEL);
    float4* xsv = (float4*)xs;
    for (int i = threadIdx.x; i < 8 * D_MODEL / 4; i += 256) xsv[i] = xg[i];
    __syncthreads();

    int r = threadIdx.x >> 5;
    int c = threadIdx.x & 31;
    const float* W = (c < 16) ? (Wb + (size_t)c * D_MODEL)
                              : (Wc + (size_t)(c - 16) * D_MODEL);
    const float4* Wv = (const float4*)W;
    const float4* xr = (const float4*)xs[r];
    float s = 0.f;
#pragma unroll 4
    for (int k = 0; k < D_MODEL / 4; k++) {
        float4 w = Wv[k], v = xr[k];
        s += w.x * v.x + w.y * v.y + w.z * v.z + w.w * v.w;
    }
    if (c < 16) Bm[(size_t)(row0 + r) * D_STATE + c]        = s;
    else        Cm[(size_t)(row0 + r) * D_STATE + (c - 16)] = s;
}

// ======== SSM scan: TCH=32 double-buffered (proven); reads combined buffer ========
#define TCH 32
__global__ __launch_bounds__(128)
void ssm_scan(const float* __restrict__ xpc,
              const float* __restrict__ Bm, const float* __restrict__ Cm,
              const float* __restrict__ Amat, const float* __restrict__ Dvec,
              float* __restrict__ yout) {
    __shared__ float  xp_s[2][TCH][64];
    __shared__ float  dt_s[2][TCH][64];
    __shared__ float4 B_s [2][TCH][4];
    __shared__ float4 C_s [2][TCH][4];

    const int tid = threadIdx.x;
    const int wid = tid >> 5, lid = tid & 31;
    const int ch   = wid * 16 + (lid & 15);      // 0..63 local channel
    const int half = lid >> 4;                   // states [0,8) or [8,16)
    const int d0 = blockIdx.x * 64;
    const int d  = d0 + ch;
    const int b  = blockIdx.y;

    float Ar[8], h[8];
#pragma unroll
    for (int j = 0; j < 8; j++) {
        Ar[j] = Amat[(size_t)d * D_STATE + half * 8 + j];
        h[j]  = 0.f;
    }
    const float Dd = Dvec[d];

    const int tt0 = tid >> 4;            // 0..7
    const int seg = (tid & 15) * 4;      // float offset within 64-ch row

    auto issue_chunk = [&](int buf, int tc) {
#pragma unroll
        for (int r = 0; r < 4; r++) {
            int tt = tt0 + r * 8;
            size_t row = (size_t)b * SEQ + tc + tt;
            cp16(s2u(&xp_s[buf][tt][seg]), xpc + row * NCOMB + d0 + seg);
            cp16(s2u(&dt_s[buf][tt][seg]), xpc + row * NCOMB + SPLIT_COL + d0 + seg);
        }
        size_t bcbase = ((size_t)b * SEQ + tc) * D_STATE;
        cp16(s2u((float*)B_s[buf] + tid * 4), Bm + bcbase + tid * 4);
        cp16(s2u((float*)C_s[buf] + tid * 4), Cm + bcbase + tid * 4);
        asm volatile("cp.async.commit_group;" ::: "memory");
    };

    issue_chunk(0, 0);
    const int NCH = SEQ / TCH;
    for (int c = 0; c < NCH; c++) {
        const int buf = c & 1;
        if (c + 1 < NCH) {
            issue_chunk(buf ^ 1, (c + 1) * TCH);
            asm volatile("cp.async.wait_group 1;" ::: "memory");
        } else {
            asm volatile("cp.async.wait_group 0;" ::: "memory");
        }
        __syncthreads();

        const int tcg = c * TCH;
#pragma unroll 4
        for (int tt = 0; tt < TCH; tt++) {
            float u  = xp_s[buf][tt][ch];
            float dv = dt_s[buf][tt][ch];
            float4 Bv0 = B_s[buf][tt][half * 2];
            float4 Bv1 = B_s[buf][tt][half * 2 + 1];
            float4 Cv0 = C_s[buf][tt][half * 2];
            float4 Cv1 = C_s[buf][tt][half * 2 + 1];
            float bs[8] = {Bv0.x, Bv0.y, Bv0.z, Bv0.w, Bv1.x, Bv1.y, Bv1.z, Bv1.w};
            float cs[8] = {Cv0.x, Cv0.y, Cv0.z, Cv0.w, Cv1.x, Cv1.y, Cv1.z, Cv1.w};
            float u01 = 0.1f * u;
            float adt = 0.1f * dv;
            float p0 = 0.f, p1 = 0.f;
#pragma unroll
            for (int j = 0; j < 8; j++) {
                float hv = h[j];
                hv = fmaf(hv * Ar[j], adt, fmaf(bs[j], u01, hv));
                h[j] = hv;
                float p = hv * cs[j];
                if (j & 1) p1 += p; else p0 += p;
            }
            float part = p0 + p1;
            float tot = part + __shfl_xor_sync(0xffffffffu, part, 16);
            if (!half)
                yout[((size_t)b * SEQ + tcg + tt) * D_INNER + d] = Dd * u + tot;
        }
        __syncthreads();
    }
}

// ---------------- gate multiply -> fp16 y (4 elems/thread) ----------------
__global__ void gate_mul(const float* __restrict__ y, const float* __restrict__ xpc,
                         __half* __restrict__ yf16) {
    int i = blockIdx.x * 256 + threadIdx.x;        // quad index
    int row = i / (D_INNER / 4);
    int dq  = i - row * (D_INNER / 4);
    float4 yv = ((const float4*)y)[i];
    const float4 gv = *(const float4*)&xpc[(size_t)row * NCOMB + D_INNER + dq * 4];
    float va = yv.x * (1.f / (1.f + expf(-gv.x)));
    float vb = yv.y * (1.f / (1.f + expf(-gv.y)));
    float vc = yv.z * (1.f / (1.f + expf(-gv.z)));
    float vd = yv.w * (1.f / (1.f + expf(-gv.w)));
    ((uint2*)yf16)[i] = make_uint2(pack_hf2(va, vb), pack_hf2(vc, vd));
}

// -------- layernorm: out = post? + LN(in + res?) * g + b (+ fp16 emit) --------
__device__ __forceinline__ float block_reduce(float v, float* red) {
    for (int o = 16; o > 0; o >>= 1) v += __shfl_down_sync(0xffffffffu, v, o);
    if ((threadIdx.x & 31) == 0) red[threadIdx.x >> 5] = v;
    __syncthreads();
    float t = 0.f;
#pragma unroll
    for (int w = 0; w < 8; w++) t += red[w];
    return t;
}

__global__ __launch_bounds__(256)
void ln_kernel(const float* __restrict__ in, const float* __restrict__ res,
               const float* __restrict__ post,
               const float* __restrict__ g, const float* __restrict__ b,
               float* __restrict__ out, __half* __restrict__ of16) {
    __shared__ float red[8];
    const int row = blockIdx.x;
    const int t   = threadIdx.x;
    float v[3], pv[3];
    float s = 0.f;
#pragma unroll
    for (int i = 0; i < 3; i++) {
        int c = t + i * 256;
        float x = in[(size_t)row * D_MODEL + c];
        if (res) x += res[(size_t)row * D_MODEL + c];
        pv[i] = post ? post[(size_t)row * D_MODEL + c] : 0.f;
        v[i] = x;
        s += x;
    }
    float tot = block_reduce(s, red);
    float mu = tot * (1.f / D_MODEL);
    __syncthreads();
    float q = 0.f;
#pragma unroll
    for (int i = 0; i < 3; i++) {
        float dd = v[i] - mu;
        q += dd * dd;
    }
    float qtot = block_reduce(q, red);
    float rs = rsqrtf(qtot * (1.f / D_MODEL) + LN_EPS);
#pragma unroll
    for (int i = 0; i < 3; i++) {
        int c = t + i * 256;
        float o = pv[i] + (v[i] - mu) * rs * g[c] + b[c];
        size_t idx = (size_t)row * D_MODEL + c;
        out[idx] = o;
        of16[idx] = __float2half(o);
    }
}

// ---------------- launch ----------------
extern "C" void kernel_launch(void* const* d_in, const int* in_sizes, int n_in,
                              void* d_out, int out_size) {
    const int*   input_ids = (const int*)  d_in[0];
    const float* emb       = (const float*)d_in[1];
    const float* W_in      = (const float*)d_in[2];   // [2, 3072, 768]
    const float* W_dt      = (const float*)d_in[3];   // [2, 1536, 768]
    const float* b_dt      = (const float*)d_in[4];
    const float* dt_bias   = (const float*)d_in[5];
    const float* W_B       = (const float*)d_in[6];
    const float* W_C       = (const float*)d_in[7];
    const float* Amat      = (const float*)d_in[8];
    const float* Dvec      = (const float*)d_in[9];
    const float* W_out     = (const float*)d_in[10];  // [2, 768, 1536]
    const float* ln_g      = (const float*)d_in[11];
    const float* ln_b      = (const float*)d_in[12];
    const float* fin_g     = (const float*)d_in[13];
    const float* fin_b     = (const float*)d_in[14];
    float* logits = (float*)d_out;                    // [4096, 32000]

    float *x, *xpc, *Bm, *Cm, *y, *o;
    __half *xf16, *yf16, *wcf16, *wof16, *ef16;
    cudaGetSymbolAddress((void**)&x,   g_x);
    cudaGetSymbolAddress((void**)&xpc, g_xpc);
    cudaGetSymbolAddress((void**)&Bm,  g_Bm);
    cudaGetSymbolAddress((void**)&Cm,  g_Cm);
    cudaGetSymbolAddress((void**)&y,   g_y);
    cudaGetSymbolAddress((void**)&o,   g_o);
    cudaGetSymbolAddress((void**)&xf16, g_xf16);
    cudaGetSymbolAddress((void**)&yf16, g_yf16);
    cudaGetSymbolAddress((void**)&wcf16, g_wcf16);
    cudaGetSymbolAddress((void**)&wof16, g_wof16);
    cudaGetSymbolAddress((void**)&ef16, g_ef16);

    cudaFuncSetAttribute(gemm_fp16, cudaFuncAttributeMaxDynamicSharedMemorySize,
                         GEMM16_SMEM);

    embed_kernel<<<NTOK, D_MODEL / 4>>>(input_ids, emb, x, xf16);

    // hoisted fp16 weight converts (combined [W_in | W_dt] per layer)
    for (int l = 0; l < N_LAYERS; l++) {
        int n4 = 2 * D_INNER * D_MODEL / 4;
        conv_fp16_kernel<<<(n4 + 255) / 256, 256>>>(
            W_in + (size_t)l * 2 * D_INNER * D_MODEL,
            wcf16 + (size_t)l * NCOMB * D_MODEL, n4);
        n4 = D_INNER * D_MODEL / 4;
        conv_fp16_kernel<<<(n4 + 255) / 256, 256>>>(
            W_dt + (size_t)l * D_INNER * D_MODEL,
            wcf16 + (size_t)l * NCOMB * D_MODEL + (size_t)SPLIT_COL * D_MODEL, n4);
    }
    {
        int n4 = N_LAYERS * D_MODEL * D_INNER / 4;
        conv_fp16_kernel<<<(n4 + 255) / 256, 256>>>(W_out, wof16, n4);
        n4 = VOCAB * D_MODEL / 4;
        conv_fp16_kernel<<<(n4 + 255) / 256, 256>>>(emb, ef16, n4);
    }

    for (int l = 0; l < N_LAYERS; l++) {
        const size_t oWc = (size_t)l * NCOMB * D_MODEL;
        const size_t oWo = (size_t)l * D_MODEL * D_INNER;
        const float* bd = b_dt    + (size_t)l * D_INNER;
        const float* db = dt_bias + (size_t)l * D_INNER;
        const float* Wb = W_B   + (size_t)l * D_STATE * D_MODEL;
        const float* Wc = W_C   + (size_t)l * D_STATE * D_MODEL;
        const float* Al = Amat  + (size_t)l * D_INNER * D_STATE;
        const float* Dl = Dvec  + (size_t)l * D_INNER;
        const float* lg = ln_g  + (size_t)l * D_MODEL;
        const float* lb = ln_b  + (size_t)l * D_MODEL;

        // [xp | gate | dt] = x @ [W_in ; W_dt]^T : [4096, 4608], softplus fused
        gemm_fp16<<<dim3(NTOK / 128, NCOMB / 128), 256, GEMM16_SMEM>>>(
            xf16, wcf16 + oWc, xpc, NTOK, NCOMB, D_MODEL, 1, bd, db);
        bc_gemm<<<NTOK / 8, 256>>>(x, Wb, Wc, Bm, Cm);
        ssm_scan<<<dim3(D_INNER / 64, BATCH), 128>>>(xpc, Bm, Cm, Al, Dl, y);
        gate_mul<<<NTOK * D_INNER / 4 / 256, 256>>>(y, xpc, yf16);
        // o = (y*gate) @ W_out^T : [4096, 768], K=1536
        gemm_fp16<<<dim3(NTOK / 128, D_MODEL / 128), 256, GEMM16_SMEM>>>(
            yf16, wof16 + oWo, o, NTOK, D_MODEL, D_INNER, 0, nullptr, nullptr);
        // x <- x + LN(o + x)  (emit fp16 x for next layer's GEMMs)
        ln_kernel<<<NTOK, 256>>>(o, x, x, lg, lb, x, xf16);
    }

    // final LN (emit fp16 x for logits GEMM)
    ln_kernel<<<NTOK, 256>>>(x, nullptr, nullptr, fin_g, fin_b, x, xf16);
    // logits = x @ emb^T : [4096, 32000]  (plain fp16, 2-stage pipeline)
    gemm_fp16<<<dim3(NTOK / 128, VOCAB / 128), 256, GEMM16_SMEM>>>(
        xf16, ef16, logits, NTOK, VOCAB, D_MODEL, 0, nullptr, nullptr);
}